// round 1
// baseline (speedup 1.0000x reference)
#include <cuda_runtime.h>
#include <math.h>

// ---------------- problem constants ----------------
constexpr int BATCH = 64;
constexpr int TFULL = 2049;
constexpr int TCTX  = 2048;
constexpr int D     = 512;
constexpr int D2    = 1024;
constexpr int VOCAB = 50257;
constexpr int KSEL  = 3;
constexpr int MTOK  = BATCH * TFULL;   // 131136

// ---------------- scratch (device globals; no allocation allowed) ----------------
__device__ float g_H  [(size_t)MTOK * D];    // h, then x = h + ff (in-place)
__device__ float g_A1 [(size_t)MTOK * D2];   // relu(h@W1+b1)
__device__ float g_HID[(size_t)MTOK * D];    // layernorm output
__device__ float g_PERT[BATCH * TCTX];       // (gate+gumbel)/T
__device__ int   g_IDX [BATCH * KSEL];
__device__ float g_CTX [BATCH * D];

// ---------------- kernel 0: embedding gather ----------------
__global__ void gather_kernel(const int* __restrict__ seq,
                              const float* __restrict__ embed)
{
    int m = blockIdx.x;            // token row
    int tid = threadIdx.x;         // 128 threads, one float4 each (D=512)
    int tok = seq[m];
    const float4* src = reinterpret_cast<const float4*>(embed + (size_t)tok * D);
    float4* dst = reinterpret_cast<float4*>(g_H + (size_t)m * D);
    dst[tid] = src[tid];
}

// ---------------- GEMM: C = epilogue(A @ Bw + bias), fp32, f32x2 inner loop ----------------
// A: [M,K] row-major, Bw: [K,N] row-major.  BM=BN=128, BK=16, 256 threads, 8x8 per-thread tile
// packed into 8x4 f32x2 accumulators.
template<bool RELU, bool ADDIN>
__global__ __launch_bounds__(256) void gemm_f32x2(
    const float* __restrict__ A, const float* __restrict__ Bw,
    const float* __restrict__ bias, const float* __restrict__ addsrc,
    float* __restrict__ C, int M, int N, int K)
{
    constexpr int BM = 128, BN = 128, BK = 16;
    __shared__ float As[BK][BM];   // stored transposed: [k][m]
    __shared__ float Bs[BK][BN];   // [k][n]

    const int tid = threadIdx.x;
    const int tx  = tid & 15;      // column group (8 cols = 4 f32x2 pairs)
    const int ty  = tid >> 4;      // row group (8 rows)
    const int m0  = blockIdx.y * BM;
    const int n0  = blockIdx.x * BN;

    const int ar  = tid >> 2, ac = tid & 3;     // A tile loader mapping
    const int brr = tid >> 5, bcc = tid & 31;   // B tile loader mapping

    unsigned long long acc[8][4];
    #pragma unroll
    for (int i = 0; i < 8; i++)
        #pragma unroll
        for (int j = 0; j < 4; j++) acc[i][j] = 0ull;   // (0.0f, 0.0f)

    for (int k0 = 0; k0 < K; k0 += BK) {
        // load A tile (transposed into smem), guarded on M
        #pragma unroll
        for (int i = 0; i < 2; i++) {
            int m = m0 + ar + i * 64;
            float4 v = make_float4(0.f, 0.f, 0.f, 0.f);
            if (m < M)
                v = *reinterpret_cast<const float4*>(A + (size_t)m * K + (k0 + ac * 4));
            As[ac * 4 + 0][ar + i * 64] = v.x;
            As[ac * 4 + 1][ar + i * 64] = v.y;
            As[ac * 4 + 2][ar + i * 64] = v.z;
            As[ac * 4 + 3][ar + i * 64] = v.w;
        }
        // load B tile (N always divisible by 128, K by 16 here)
        #pragma unroll
        for (int i = 0; i < 2; i++) {
            int kk = brr + i * 8;
            *reinterpret_cast<float4*>(&Bs[kk][bcc * 4]) =
                *reinterpret_cast<const float4*>(Bw + (size_t)(k0 + kk) * N + (n0 + bcc * 4));
        }
        __syncthreads();

        #pragma unroll
        for (int kk = 0; kk < BK; kk++) {
            unsigned long long aa[8];
            #pragma unroll
            for (int i = 0; i < 8; i++) {
                unsigned u = __float_as_uint(As[kk][ty * 8 + i]);
                asm("mov.b64 %0, {%1, %1};" : "=l"(aa[i]) : "r"(u));
            }
            const unsigned long long* bp =
                reinterpret_cast<const unsigned long long*>(&Bs[kk][tx * 8]);
            unsigned long long bb[4];
            #pragma unroll
            for (int j = 0; j < 4; j++) bb[j] = bp[j];

            #pragma unroll
            for (int i = 0; i < 8; i++)
                #pragma unroll
                for (int j = 0; j < 4; j++)
                    asm("fma.rn.f32x2 %0, %1, %2, %0;"
                        : "+l"(acc[i][j]) : "l"(aa[i]), "l"(bb[j]));
        }
        __syncthreads();
    }

    // epilogue
    #pragma unroll
    for (int i = 0; i < 8; i++) {
        int m = m0 + ty * 8 + i;
        if (m >= M) continue;
        #pragma unroll
        for (int j = 0; j < 4; j++) {
            unsigned lo, hi;
            asm("mov.b64 {%0, %1}, %2;" : "=r"(lo), "=r"(hi) : "l"(acc[i][j]));
            int n = n0 + tx * 8 + j * 2;
            float v0 = __uint_as_float(lo) + bias[n];
            float v1 = __uint_as_float(hi) + bias[n + 1];
            if (RELU) { v0 = fmaxf(v0, 0.f); v1 = fmaxf(v1, 0.f); }
            if (ADDIN) {
                v0 += addsrc[(size_t)m * N + n];
                v1 += addsrc[(size_t)m * N + n + 1];
            }
            C[(size_t)m * N + n]     = v0;
            C[(size_t)m * N + n + 1] = v1;
        }
    }
}

// ---------------- kernel 3: layernorm + gate + perturb ----------------
__global__ __launch_bounds__(256) void ln_gate_kernel(
    const float* __restrict__ gamma, const float* __restrict__ beta,
    const float* __restrict__ Wg, const float* __restrict__ bgp,
    const float* __restrict__ gumbel, const float* __restrict__ temp)
{
    int m = blockIdx.x, tid = threadIdx.x;   // 256 threads, 2 elems each
    const float* x = g_H + (size_t)m * D;
    float x0 = x[tid], x1 = x[tid + 256];
    float s = x0 + x1;
    float q = x0 * x0 + x1 * x1;
    #pragma unroll
    for (int o = 16; o > 0; o >>= 1) {
        s += __shfl_down_sync(0xffffffffu, s, o);
        q += __shfl_down_sync(0xffffffffu, q, o);
    }
    __shared__ float sh[16];
    __shared__ float s_stats[2];
    int lane = tid & 31, w = tid >> 5;
    if (lane == 0) { sh[w] = s; sh[w + 8] = q; }
    __syncthreads();
    if (tid == 0) {
        float S = 0.f, Q = 0.f;
        for (int i = 0; i < 8; i++) { S += sh[i]; Q += sh[i + 8]; }
        float mu  = S * (1.f / 512.f);
        float var = Q * (1.f / 512.f) - mu * mu;
        s_stats[0] = mu;
        s_stats[1] = rsqrtf(var + 1e-5f);
    }
    __syncthreads();
    float mu = s_stats[0], rs = s_stats[1];
    float h0 = (x0 - mu) * rs * gamma[tid] + beta[tid];
    float h1 = (x1 - mu) * rs * gamma[tid + 256] + beta[tid + 256];
    g_HID[(size_t)m * D + tid]       = h0;
    g_HID[(size_t)m * D + tid + 256] = h1;

    float g = h0 * Wg[tid] + h1 * Wg[tid + 256];
    #pragma unroll
    for (int o = 16; o > 0; o >>= 1) g += __shfl_down_sync(0xffffffffu, g, o);
    if (lane == 0) sh[w] = g;
    __syncthreads();
    if (tid == 0) {
        float G = 0.f;
        for (int i = 0; i < 8; i++) G += sh[i];
        int b = m / TFULL, t = m % TFULL;
        if (t < TCTX)
            g_PERT[b * TCTX + t] = (G + bgp[0] + gumbel[b * TCTX + t]) / temp[0];
    }
}

// ---------------- kernel 4: per-row top-3 ----------------
__global__ void top3_kernel()
{
    int b = blockIdx.x, tid = threadIdx.x;   // 256 threads
    float bv[3] = {-1e30f, -1e30f, -1e30f};
    int   bi[3] = {0, 0, 0};
    for (int t = tid; t < TCTX; t += 256) {
        float v = g_PERT[b * TCTX + t];
        if (v > bv[0]) { bv[2]=bv[1]; bi[2]=bi[1]; bv[1]=bv[0]; bi[1]=bi[0]; bv[0]=v; bi[0]=t; }
        else if (v > bv[1]) { bv[2]=bv[1]; bi[2]=bi[1]; bv[1]=v; bi[1]=t; }
        else if (v > bv[2]) { bv[2]=v; bi[2]=t; }
    }
    __shared__ float sv[768];
    __shared__ int   si[768];
    sv[tid*3+0]=bv[0]; sv[tid*3+1]=bv[1]; sv[tid*3+2]=bv[2];
    si[tid*3+0]=bi[0]; si[tid*3+1]=bi[1]; si[tid*3+2]=bi[2];
    __syncthreads();
    if (tid == 0) {
        float rv[3] = {-1e30f, -1e30f, -1e30f};
        int   ri[3] = {0, 0, 0};
        for (int e = 0; e < 768; e++) {
            float v = sv[e]; int i = si[e];
            if (v > rv[0]) { rv[2]=rv[1]; ri[2]=ri[1]; rv[1]=rv[0]; ri[1]=ri[0]; rv[0]=v; ri[0]=i; }
            else if (v > rv[1]) { rv[2]=rv[1]; ri[2]=ri[1]; rv[1]=v; ri[1]=i; }
            else if (v > rv[2]) { rv[2]=v; ri[2]=i; }
        }
        g_IDX[b*3+0]=ri[0]; g_IDX[b*3+1]=ri[1]; g_IDX[b*3+2]=ri[2];
    }
}

// ---------------- kernel 5: q = h_last@Wr+br; scores; softmax over 16 slots; ctx ----------------
__global__ __launch_bounds__(512) void attn_kernel(
    const float* __restrict__ Wr, const float* __restrict__ br)
{
    int b = blockIdx.x, tid = threadIdx.x;   // 512 threads (one per d)
    __shared__ float hlast[D];
    __shared__ float gh[3][D];
    __shared__ float red[48];
    __shared__ float s_attn[3];
    size_t base = (size_t)b * TFULL * D;
    hlast[tid] = g_HID[base + (size_t)TCTX * D + tid];
    int i0 = g_IDX[b*3+0], i1 = g_IDX[b*3+1], i2 = g_IDX[b*3+2];
    gh[0][tid] = g_HID[base + (size_t)i0 * D + tid];
    gh[1][tid] = g_HID[base + (size_t)i1 * D + tid];
    gh[2][tid] = g_HID[base + (size_t)i2 * D + tid];
    __syncthreads();

    float qv = br[tid];
    #pragma unroll 4
    for (int j = 0; j < D; j++)
        qv += hlast[j] * Wr[(size_t)j * D + tid];

    float p0 = gh[0][tid] * qv, p1 = gh[1][tid] * qv, p2 = gh[2][tid] * qv;
    #pragma unroll
    for (int o = 16; o > 0; o >>= 1) {
        p0 += __shfl_down_sync(0xffffffffu, p0, o);
        p1 += __shfl_down_sync(0xffffffffu, p1, o);
        p2 += __shfl_down_sync(0xffffffffu, p2, o);
    }
    int lane = tid & 31, w = tid >> 5;
    if (lane == 0) { red[w] = p0; red[16 + w] = p1; red[32 + w] = p2; }
    __syncthreads();
    if (tid == 0) {
        float s0 = 0.f, s1 = 0.f, s2 = 0.f;
        for (int i = 0; i < 16; i++) { s0 += red[i]; s1 += red[16+i]; s2 += red[32+i]; }
        // 16 slots: 3 real scores + 13 exact zeros (empty slots)
        float mx = fmaxf(fmaxf(s0, s1), fmaxf(s2, 0.f));
        float e0 = expf(s0 - mx), e1 = expf(s1 - mx), e2 = expf(s2 - mx);
        float den = e0 + e1 + e2 + 13.f * expf(-mx);
        s_attn[0] = e0 / den; s_attn[1] = e1 / den; s_attn[2] = e2 / den;
    }
    __syncthreads();
    g_CTX[b * D + tid] = s_attn[0]*gh[0][tid] + s_attn[1]*gh[1][tid] + s_attn[2]*gh[2][tid];
}

// ---------------- kernel 6: out = ctx @ Wo + bo   (64 x 50257, K=512) ----------------
__global__ __launch_bounds__(128) void out_gemm(
    const float* __restrict__ Wo, const float* __restrict__ bo,
    float* __restrict__ out)
{
    __shared__ float sc[16 * 512];           // 32 KB: 16 rows of ctx
    int tid = threadIdx.x;                   // 128 threads
    int n = blockIdx.x * 128 + tid;
    float bias = (n < VOCAB) ? bo[n] : 0.f;

    for (int mt = 0; mt < 4; mt++) {
        __syncthreads();
        for (int i = tid; i < 16 * 512; i += 128)
            sc[i] = g_CTX[mt * 16 * 512 + i];
        __syncthreads();
        if (n < VOCAB) {
            float acc[16];
            #pragma unroll
            for (int m2 = 0; m2 < 16; m2++) acc[m2] = 0.f;
            for (int k = 0; k < 512; k += 4) {
                float w0 = Wo[(size_t)(k + 0) * VOCAB + n];
                float w1 = Wo[(size_t)(k + 1) * VOCAB + n];
                float w2 = Wo[(size_t)(k + 2) * VOCAB + n];
                float w3 = Wo[(size_t)(k + 3) * VOCAB + n];
                #pragma unroll
                for (int m2 = 0; m2 < 16; m2++) {
                    float4 c = *reinterpret_cast<const float4*>(&sc[m2 * 512 + k]);
                    acc[m2] += c.x * w0 + c.y * w1 + c.z * w2 + c.w * w3;
                }
            }
            #pragma unroll
            for (int m2 = 0; m2 < 16; m2++)
                out[(size_t)(mt * 16 + m2) * VOCAB + n] = acc[m2] + bias;
        }
    }
}

// ---------------- launch ----------------
extern "C" void kernel_launch(void* const* d_in, const int* in_sizes, int n_in,
                              void* d_out, int out_size)
{
    const int*   seq    = (const int*)  d_in[0];
    const float* temp   = (const float*)d_in[1];
    const float* gumbel = (const float*)d_in[2];
    const float* embed  = (const float*)d_in[3];
    const float* W1     = (const float*)d_in[4];
    const float* b1     = (const float*)d_in[5];
    const float* W2     = (const float*)d_in[6];
    const float* b2     = (const float*)d_in[7];
    const float* gamma  = (const float*)d_in[8];
    const float* beta   = (const float*)d_in[9];
    const float* Wg     = (const float*)d_in[10];
    const float* bg     = (const float*)d_in[11];
    const float* Wr     = (const float*)d_in[12];
    const float* br     = (const float*)d_in[13];
    const float* Wo     = (const float*)d_in[14];
    const float* bo     = (const float*)d_in[15];
    float* out = (float*)d_out;

    float *pH = nullptr, *pA1 = nullptr;
    cudaGetSymbolAddress((void**)&pH,  g_H);
    cudaGetSymbolAddress((void**)&pA1, g_A1);

    // 1. gather embeddings
    gather_kernel<<<MTOK, 128>>>(seq, embed);

    // 2. A1 = relu(H @ W1 + b1)     [131136 x 1024]
    gemm_f32x2<true, false><<<dim3(D2 / 128, (MTOK + 127) / 128), 256>>>(
        pH, W1, b1, nullptr, pA1, MTOK, D2, D);

    // 3. X = A1 @ W2 + b2 + H  (in-place into g_H)   [131136 x 512]
    gemm_f32x2<false, true><<<dim3(D / 128, (MTOK + 127) / 128), 256>>>(
        pA1, W2, b2, pH, pH, MTOK, D, D2);

    // 4. layernorm + gate + perturbed
    ln_gate_kernel<<<MTOK, 256>>>(gamma, beta, Wg, bg, gumbel, temp);

    // 5. top-3 per batch row
    top3_kernel<<<BATCH, 256>>>();

    // 6. memory attention -> ctx
    attn_kernel<<<BATCH, 512>>>(Wr, br);

    // 7. out = ctx @ Wo + bo
    out_gemm<<<(VOCAB + 127) / 128, 128>>>(Wo, bo, out);
}

// round 3
// speedup vs baseline: 2.8268x; 2.8268x over previous
#include <cuda_runtime.h>
#include <cuda_bf16.h>
#include <math.h>
#include <cstdint>

// ---------------- problem constants ----------------
constexpr int BATCH = 64;
constexpr int TFULL = 2049;
constexpr int TCTX  = 2048;
constexpr int D     = 512;
constexpr int D2    = 1024;
constexpr int VOCAB = 50257;
constexpr int MTOK  = BATCH * TFULL;   // 131136

// ---------------- scratch (device globals) ----------------
__device__ float          g_H  [(size_t)MTOK * D];    // h, then x = h + ff
__device__ __nv_bfloat16  g_Hh [(size_t)MTOK * D];
__device__ __nv_bfloat16  g_Hl [(size_t)MTOK * D];
__device__ __nv_bfloat16  g_A1h[(size_t)MTOK * D2];
__device__ __nv_bfloat16  g_A1l[(size_t)MTOK * D2];
__device__ __nv_bfloat16  g_W1h[(size_t)D2 * D];      // W1^T split  [N=D2, K=D]
__device__ __nv_bfloat16  g_W1l[(size_t)D2 * D];
__device__ __nv_bfloat16  g_W2h[(size_t)D * D2];      // W2^T split  [N=D,  K=D2]
__device__ __nv_bfloat16  g_W2l[(size_t)D * D2];
__device__ float          g_HID[(size_t)MTOK * D];
__device__ float          g_PERT[BATCH * TCTX];
__device__ int            g_IDX [BATCH * 3];
__device__ float          g_CTX [BATCH * D];

// ---------------- PTX helpers (base-target features only) ----------------
__device__ __forceinline__ unsigned smem_u32(const void* p) {
    unsigned a;
    asm("{ .reg .u64 t; cvta.to.shared.u64 t, %1; cvt.u32.u64 %0, t; }" : "=r"(a) : "l"(p));
    return a;
}
__device__ __forceinline__ void cp16(unsigned dst, const void* src, int sz) {
    asm volatile("cp.async.cg.shared.global [%0], [%1], 16, %2;"
                 :: "r"(dst), "l"(src), "r"(sz) : "memory");
}
__device__ __forceinline__ void ldsm4(unsigned& r0, unsigned& r1, unsigned& r2, unsigned& r3,
                                      unsigned addr) {
    asm volatile("ldmatrix.sync.aligned.m8n8.x4.shared.b16 {%0,%1,%2,%3}, [%4];"
                 : "=r"(r0), "=r"(r1), "=r"(r2), "=r"(r3) : "r"(addr));
}
__device__ __forceinline__ void mma_bf16(float* c, const unsigned* a, const unsigned* b) {
    asm volatile("mma.sync.aligned.m16n8k16.row.col.f32.bf16.bf16.f32 "
                 "{%0,%1,%2,%3}, {%4,%5,%6,%7}, {%8,%9}, {%0,%1,%2,%3};"
                 : "+f"(c[0]), "+f"(c[1]), "+f"(c[2]), "+f"(c[3])
                 : "r"(a[0]), "r"(a[1]), "r"(a[2]), "r"(a[3]), "r"(b[0]), "r"(b[1]));
}
__device__ __forceinline__ void split_pack(float v0, float v1, unsigned& ph, unsigned& pl) {
    __nv_bfloat16 h0 = __float2bfloat16_rn(v0);
    __nv_bfloat16 h1 = __float2bfloat16_rn(v1);
    __nv_bfloat16 l0 = __float2bfloat16_rn(v0 - __bfloat162float(h0));
    __nv_bfloat16 l1 = __float2bfloat16_rn(v1 - __bfloat162float(h1));
    ph = (unsigned)__bfloat16_as_ushort(h0) | ((unsigned)__bfloat16_as_ushort(h1) << 16);
    pl = (unsigned)__bfloat16_as_ushort(l0) | ((unsigned)__bfloat16_as_ushort(l1) << 16);
}

// ---------------- weight prep: transpose + bf16 split ----------------
__global__ void wprep(const float* __restrict__ W,
                      __nv_bfloat16* __restrict__ Bh, __nv_bfloat16* __restrict__ Bl,
                      int K, int N)
{
    int i = blockIdx.x * 256 + threadIdx.x;
    if (i >= K * N) return;
    int k = i / N, n = i - k * N;
    float v = W[i];
    __nv_bfloat16 h = __float2bfloat16_rn(v);
    __nv_bfloat16 l = __float2bfloat16_rn(v - __bfloat162float(h));
    Bh[(size_t)n * K + k] = h;
    Bl[(size_t)n * K + k] = l;
}

// ---------------- gather: embed lookup + bf16 split ----------------
__global__ void gather_kernel(const int* __restrict__ seq, const float* __restrict__ embed)
{
    int m = blockIdx.x, tid = threadIdx.x;  // 128 threads, float4 each
    int tok = seq[m];
    float4 v = reinterpret_cast<const float4*>(embed + (size_t)tok * D)[tid];
    reinterpret_cast<float4*>(g_H + (size_t)m * D)[tid] = v;
    unsigned h0, l0, h1, l1;
    split_pack(v.x, v.y, h0, l0);
    split_pack(v.z, v.w, h1, l1);
    reinterpret_cast<uint2*>(g_Hh + (size_t)m * D)[tid] = make_uint2(h0, h1);
    reinterpret_cast<uint2*>(g_Hl + (size_t)m * D)[tid] = make_uint2(l0, l1);
}

// ---------------- mma.sync split-bf16 GEMM ----------------
// C = A @ B^T (+bias, epilogue). A: [M,K] bf16 hi/lo, B: [N,K] bf16 hi/lo.
// CTA tile 128x128, 8 warps (4 M x 2 N), warp tile 32x64, BK=32, 4-stage cp.async.
// Per-stage smem: Ah[2][128][16], Al, Bh, Bl  (each 8KB, 32KB/stage).
// Slice layout: elem (row, k) of slice s at  s*4096 + row*32 + (k%16)*2   (bytes).
constexpr int STAGE_BYTES = 32768;
constexpr int GEMM_SMEM   = 4 * STAGE_BYTES;   // 131072

__device__ __forceinline__ void fill_stage(unsigned sb,
    const __nv_bfloat16* __restrict__ Ah, const __nv_bfloat16* __restrict__ Al,
    const __nv_bfloat16* __restrict__ Bh, const __nv_bfloat16* __restrict__ Bl,
    int K, int m0, int M, int n0, int kc, int tid)
{
    int m = tid >> 1, half = tid & 1;
    int arow = m0 + m;
    int asz  = (arow < M) ? 16 : 0;
    size_t aoff = (size_t)(asz ? arow : 0) * K + kc + half * 8;
    size_t boff = (size_t)(n0 + m) * K + kc + half * 8;
    unsigned dst = sb + m * 32 + half * 16;
    #pragma unroll
    for (int s = 0; s < 2; s++) {
        cp16(dst + s * 4096,         Ah + aoff + s * 16, asz);
        cp16(dst + 8192 + s * 4096,  Al + aoff + s * 16, asz);
        cp16(dst + 16384 + s * 4096, Bh + boff + s * 16, 16);
        cp16(dst + 24576 + s * 4096, Bl + boff + s * 16, 16);
    }
    asm volatile("cp.async.commit_group;" ::: "memory");
}

// MODE 0: relu + bf16 hi/lo split out.  MODE 1: + bias + addsrc, fp32 out.
template<int MODE>
__global__ __launch_bounds__(256, 1) void ff_gemm(
    const __nv_bfloat16* __restrict__ Ah, const __nv_bfloat16* __restrict__ Al,
    const __nv_bfloat16* __restrict__ Bh, const __nv_bfloat16* __restrict__ Bl,
    const float* __restrict__ bias, const float* __restrict__ addsrc,
    __nv_bfloat16* __restrict__ Ch, __nv_bfloat16* __restrict__ Cl,
    float* __restrict__ Cf, int M, int N, int K)
{
    extern __shared__ __align__(128) char smem[];
    unsigned sb = smem_u32(smem);
    const int tid = threadIdx.x, lane = tid & 31, wid = tid >> 5;
    const int wm = wid & 3, wn = wid >> 2;
    const int m0 = blockIdx.y * 128, n0 = blockIdx.x * 128;

    // per-lane ldmatrix offsets (within a k-slice)
    const unsigned aO = (unsigned)((wm * 32 + (lane & 15)) * 32 + (lane >> 4) * 16);
    const unsigned bO = 16384u +
        (unsigned)((wn * 64 + (lane >> 4) * 8 + (lane & 7)) * 32 + ((lane >> 3) & 1) * 16);

    float acc[2][8][4];
    #pragma unroll
    for (int i = 0; i < 2; i++)
        #pragma unroll
        for (int j = 0; j < 8; j++)
            #pragma unroll
            for (int q = 0; q < 4; q++) acc[i][j][q] = 0.f;

    const int NC = K >> 5;
    fill_stage(sb + 0 * STAGE_BYTES, Ah, Al, Bh, Bl, K, m0, M, n0, 0,  tid);
    fill_stage(sb + 1 * STAGE_BYTES, Ah, Al, Bh, Bl, K, m0, M, n0, 32, tid);
    fill_stage(sb + 2 * STAGE_BYTES, Ah, Al, Bh, Bl, K, m0, M, n0, 64, tid);

    for (int c = 0; c < NC; c++) {
        int rem = NC - 1 - c;
        if (rem >= 2)      asm volatile("cp.async.wait_group 2;" ::: "memory");
        else if (rem == 1) asm volatile("cp.async.wait_group 1;" ::: "memory");
        else               asm volatile("cp.async.wait_group 0;" ::: "memory");
        __syncthreads();

        int pf = c + 3;
        if (pf < NC)
            fill_stage(sb + (pf & 3) * STAGE_BYTES, Ah, Al, Bh, Bl, K, m0, M, n0, pf * 32, tid);

        unsigned st = sb + (c & 3) * STAGE_BYTES;
        #pragma unroll
        for (int ks = 0; ks < 2; ks++) {
            unsigned sl = st + ks * 4096;
            unsigned ah[2][4], al[2][4], bh[8][2], bl[8][2];
            #pragma unroll
            for (int mt = 0; mt < 2; mt++) {
                ldsm4(ah[mt][0], ah[mt][1], ah[mt][2], ah[mt][3], sl + aO + mt * 512);
                ldsm4(al[mt][0], al[mt][1], al[mt][2], al[mt][3], sl + 8192 + aO + mt * 512);
            }
            #pragma unroll
            for (int pr = 0; pr < 4; pr++) {
                ldsm4(bh[2*pr][0], bh[2*pr][1], bh[2*pr+1][0], bh[2*pr+1][1],
                      sl + bO + pr * 512);
                ldsm4(bl[2*pr][0], bl[2*pr][1], bl[2*pr+1][0], bl[2*pr+1][1],
                      sl + 8192 + bO + pr * 512);
            }
            #pragma unroll
            for (int mt = 0; mt < 2; mt++)
                #pragma unroll
                for (int nt = 0; nt < 8; nt++) {
                    mma_bf16(acc[mt][nt], ah[mt], bh[nt]);
                    mma_bf16(acc[mt][nt], al[mt], bh[nt]);
                    mma_bf16(acc[mt][nt], ah[mt], bl[nt]);
                }
        }
    }

    // ---------------- epilogue ----------------
    const int g = lane >> 2, t4 = lane & 3;
    #pragma unroll
    for (int mt = 0; mt < 2; mt++) {
        int r0 = m0 + wm * 32 + mt * 16 + g;
        #pragma unroll
        for (int nt = 0; nt < 8; nt++) {
            int n = n0 + wn * 64 + nt * 8 + t4 * 2;
            float b0 = bias[n], b1 = bias[n + 1];
            if (MODE == 0) {
                if (r0 < M) {
                    float v0 = fmaxf(acc[mt][nt][0] + b0, 0.f);
                    float v1 = fmaxf(acc[mt][nt][1] + b1, 0.f);
                    unsigned ph, pl; split_pack(v0, v1, ph, pl);
                    *reinterpret_cast<unsigned*>(Ch + (size_t)r0 * N + n) = ph;
                    *reinterpret_cast<unsigned*>(Cl + (size_t)r0 * N + n) = pl;
                }
                if (r0 + 8 < M) {
                    float v0 = fmaxf(acc[mt][nt][2] + b0, 0.f);
                    float v1 = fmaxf(acc[mt][nt][3] + b1, 0.f);
                    unsigned ph, pl; split_pack(v0, v1, ph, pl);
                    *reinterpret_cast<unsigned*>(Ch + (size_t)(r0 + 8) * N + n) = ph;
                    *reinterpret_cast<unsigned*>(Cl + (size_t)(r0 + 8) * N + n) = pl;
                }
            } else {
                if (r0 < M) {
                    float2 a = *reinterpret_cast<const float2*>(addsrc + (size_t)r0 * N + n);
                    float2 o = make_float2(acc[mt][nt][0] + b0 + a.x,
                                           acc[mt][nt][1] + b1 + a.y);
                    *reinterpret_cast<float2*>(Cf + (size_t)r0 * N + n) = o;
                }
                if (r0 + 8 < M) {
                    float2 a = *reinterpret_cast<const float2*>(addsrc + (size_t)(r0 + 8) * N + n);
                    float2 o = make_float2(acc[mt][nt][2] + b0 + a.x,
                                           acc[mt][nt][3] + b1 + a.y);
                    *reinterpret_cast<float2*>(Cf + (size_t)(r0 + 8) * N + n) = o;
                }
            }
        }
    }
}

// ---------------- layernorm + gate + perturb ----------------
__global__ __launch_bounds__(128) void ln_gate_kernel(
    const float* __restrict__ gamma, const float* __restrict__ beta,
    const float* __restrict__ Wg, const float* __restrict__ bgp,
    const float* __restrict__ gumbel, const float* __restrict__ temp)
{
    int m = blockIdx.x, tid = threadIdx.x;   // 128 threads, float4 each
    float4 x = reinterpret_cast<const float4*>(g_H + (size_t)m * D)[tid];
    float s = x.x + x.y + x.z + x.w;
    float q = x.x*x.x + x.y*x.y + x.z*x.z + x.w*x.w;
    #pragma unroll
    for (int o = 16; o > 0; o >>= 1) {
        s += __shfl_down_sync(0xffffffffu, s, o);
        q += __shfl_down_sync(0xffffffffu, q, o);
    }
    __shared__ float sh[8];
    __shared__ float sg[4];
    int lane = tid & 31, w = tid >> 5;
    if (lane == 0) { sh[w] = s; sh[4 + w] = q; }
    __syncthreads();
    float S = sh[0] + sh[1] + sh[2] + sh[3];
    float Q = sh[4] + sh[5] + sh[6] + sh[7];
    float mu = S * (1.f / 512.f);
    float rs = rsqrtf(Q * (1.f / 512.f) - mu * mu + 1e-5f);
    float4 g4 = reinterpret_cast<const float4*>(gamma)[tid];
    float4 b4 = reinterpret_cast<const float4*>(beta)[tid];
    float4 h;
    h.x = (x.x - mu) * rs * g4.x + b4.x;
    h.y = (x.y - mu) * rs * g4.y + b4.y;
    h.z = (x.z - mu) * rs * g4.z + b4.z;
    h.w = (x.w - mu) * rs * g4.w + b4.w;
    reinterpret_cast<float4*>(g_HID + (size_t)m * D)[tid] = h;
    float4 wg = reinterpret_cast<const float4*>(Wg)[tid];
    float g = h.x*wg.x + h.y*wg.y + h.z*wg.z + h.w*wg.w;
    #pragma unroll
    for (int o = 16; o > 0; o >>= 1) g += __shfl_down_sync(0xffffffffu, g, o);
    if (lane == 0) sg[w] = g;
    __syncthreads();
    if (tid == 0) {
        float G = sg[0] + sg[1] + sg[2] + sg[3];
        int b = m / TFULL, t = m - b * TFULL;
        if (t < TCTX)
            g_PERT[b * TCTX + t] = (G + bgp[0] + gumbel[b * TCTX + t]) / temp[0];
    }
}

// ---------------- per-row top-3 ----------------
__global__ void top3_kernel()
{
    int b = blockIdx.x, tid = threadIdx.x;   // 256 threads
    float bv[3] = {-1e30f, -1e30f, -1e30f};
    int   bi[3] = {0, 0, 0};
    for (int t = tid; t < TCTX; t += 256) {
        float v = g_PERT[b * TCTX + t];
        if (v > bv[0]) { bv[2]=bv[1]; bi[2]=bi[1]; bv[1]=bv[0]; bi[1]=bi[0]; bv[0]=v; bi[0]=t; }
        else if (v > bv[1]) { bv[2]=bv[1]; bi[2]=bi[1]; bv[1]=v; bi[1]=t; }
        else if (v > bv[2]) { bv[2]=v; bi[2]=t; }
    }
    __shared__ float sv[768];
    __shared__ int   si[768];
    sv[tid*3+0]=bv[0]; sv[tid*3+1]=bv[1]; sv[tid*3+2]=bv[2];
    si[tid*3+0]=bi[0]; si[tid*3+1]=bi[1]; si[tid*3+2]=bi[2];
    __syncthreads();
    if (tid == 0) {
        float rv[3] = {-1e30f, -1e30f, -1e30f};
        int   ri[3] = {0, 0, 0};
        for (int e = 0; e < 768; e++) {
            float v = sv[e]; int i = si[e];
            if (v > rv[0]) { rv[2]=rv[1]; ri[2]=ri[1]; rv[1]=rv[0]; ri[1]=ri[0]; rv[0]=v; ri[0]=i; }
            else if (v > rv[1]) { rv[2]=rv[1]; ri[2]=ri[1]; rv[1]=v; ri[1]=i; }
            else if (v > rv[2]) { rv[2]=v; ri[2]=i; }
        }
        g_IDX[b*3+0]=ri[0]; g_IDX[b*3+1]=ri[1]; g_IDX[b*3+2]=ri[2];
    }
}

// ---------------- memory attention ----------------
__global__ __launch_bounds__(512) void attn_kernel(
    const float* __restrict__ Wr, const float* __restrict__ br)
{
    int b = blockIdx.x, tid = threadIdx.x;   // 512 threads (one per d)
    __shared__ float hlast[D];
    __shared__ float gh[3][D];
    __shared__ float red[48];
    __shared__ float s_attn[3];
    size_t base = (size_t)b * TFULL * D;
    hlast[tid] = g_HID[base + (size_t)TCTX * D + tid];
    int i0 = g_IDX[b*3+0], i1 = g_IDX[b*3+1], i2 = g_IDX[b*3+2];
    gh[0][tid] = g_HID[base + (size_t)i0 * D + tid];
    gh[1][tid] = g_HID[base + (size_t)i1 * D + tid];
    gh[2][tid] = g_HID[base + (size_t)i2 * D + tid];
    __syncthreads();

    float qv = br[tid];
    #pragma unroll 4
    for (int j = 0; j < D; j++)
        qv += hlast[j] * Wr[(size_t)j * D + tid];

    float p0 = gh[0][tid] * qv, p1 = gh[1][tid] * qv, p2 = gh[2][tid] * qv;
    #pragma unroll
    for (int o = 16; o > 0; o >>= 1) {
        p0 += __shfl_down_sync(0xffffffffu, p0, o);
        p1 += __shfl_down_sync(0xffffffffu, p1, o);
        p2 += __shfl_down_sync(0xffffffffu, p2, o);
    }
    int lane = tid & 31, w = tid >> 5;
    if (lane == 0) { red[w] = p0; red[16 + w] = p1; red[32 + w] = p2; }
    __syncthreads();
    if (tid == 0) {
        float s0 = 0.f, s1 = 0.f, s2 = 0.f;
        for (int i = 0; i < 16; i++) { s0 += red[i]; s1 += red[16+i]; s2 += red[32+i]; }
        float mx = fmaxf(fmaxf(s0, s1), fmaxf(s2, 0.f));
        float e0 = expf(s0 - mx), e1 = expf(s1 - mx), e2 = expf(s2 - mx);
        float den = e0 + e1 + e2 + 13.f * expf(-mx);
        s_attn[0] = e0 / den; s_attn[1] = e1 / den; s_attn[2] = e2 / den;
    }
    __syncthreads();
    g_CTX[b * D + tid] = s_attn[0]*gh[0][tid] + s_attn[1]*gh[1][tid] + s_attn[2]*gh[2][tid];
}

// ---------------- out = ctx @ Wo + bo  (64 x 50257, K=512) ----------------
__global__ __launch_bounds__(128) void out_gemm(
    const float* __restrict__ Wo, const float* __restrict__ bo,
    float* __restrict__ out)
{
    __shared__ float sc[16 * 512];
    int tid = threadIdx.x;
    int n = blockIdx.x * 128 + tid;
    float bias = (n < VOCAB) ? bo[n] : 0.f;

    for (int mt = 0; mt < 4; mt++) {
        __syncthreads();
        for (int i = tid; i < 16 * 512; i += 128)
            sc[i] = g_CTX[mt * 16 * 512 + i];
        __syncthreads();
        if (n < VOCAB) {
            float acc[16];
            #pragma unroll
            for (int m2 = 0; m2 < 16; m2++) acc[m2] = 0.f;
            for (int k = 0; k < 512; k += 4) {
                float w0 = Wo[(size_t)(k + 0) * VOCAB + n];
                float w1 = Wo[(size_t)(k + 1) * VOCAB + n];
                float w2 = Wo[(size_t)(k + 2) * VOCAB + n];
                float w3 = Wo[(size_t)(k + 3) * VOCAB + n];
                #pragma unroll
                for (int m2 = 0; m2 < 16; m2++) {
                    float4 c = *reinterpret_cast<const float4*>(&sc[m2 * 512 + k]);
                    acc[m2] += c.x * w0 + c.y * w1 + c.z * w2 + c.w * w3;
                }
            }
            #pragma unroll
            for (int m2 = 0; m2 < 16; m2++)
                out[(size_t)(mt * 16 + m2) * VOCAB + n] = acc[m2] + bias;
        }
    }
}

// ---------------- launch ----------------
extern "C" void kernel_launch(void* const* d_in, const int* in_sizes, int n_in,
                              void* d_out, int out_size)
{
    const int*   seq    = (const int*)  d_in[0];
    const float* temp   = (const float*)d_in[1];
    const float* gumbel = (const float*)d_in[2];
    const float* embed  = (const float*)d_in[3];
    const float* W1     = (const float*)d_in[4];
    const float* b1     = (const float*)d_in[5];
    const float* W2     = (const float*)d_in[6];
    const float* b2     = (const float*)d_in[7];
    const float* gamma  = (const float*)d_in[8];
    const float* beta   = (const float*)d_in[9];
    const float* Wg     = (const float*)d_in[10];
    const float* bg     = (const float*)d_in[11];
    const float* Wr     = (const float*)d_in[12];
    const float* br     = (const float*)d_in[13];
    const float* Wo     = (const float*)d_in[14];
    const float* bo     = (const float*)d_in[15];
    float* out = (float*)d_out;

    float *pH;
    __nv_bfloat16 *pHh, *pHl, *pA1h, *pA1l, *pW1h, *pW1l, *pW2h, *pW2l;
    cudaGetSymbolAddress((void**)&pH,   g_H);
    cudaGetSymbolAddress((void**)&pHh,  g_Hh);
    cudaGetSymbolAddress((void**)&pHl,  g_Hl);
    cudaGetSymbolAddress((void**)&pA1h, g_A1h);
    cudaGetSymbolAddress((void**)&pA1l, g_A1l);
    cudaGetSymbolAddress((void**)&pW1h, g_W1h);
    cudaGetSymbolAddress((void**)&pW1l, g_W1l);
    cudaGetSymbolAddress((void**)&pW2h, g_W2h);
    cudaGetSymbolAddress((void**)&pW2l, g_W2l);

    cudaFuncSetAttribute(ff_gemm<0>, cudaFuncAttributeMaxDynamicSharedMemorySize, GEMM_SMEM);
    cudaFuncSetAttribute(ff_gemm<1>, cudaFuncAttributeMaxDynamicSharedMemorySize, GEMM_SMEM);

    // 0. weight prep (transpose + split)
    wprep<<<(D * D2 + 255) / 256, 256>>>(W1, pW1h, pW1l, D, D2);
    wprep<<<(D2 * D + 255) / 256, 256>>>(W2, pW2h, pW2l, D2, D);

    // 1. gather embeddings (+ split)
    gather_kernel<<<MTOK, 128>>>(seq, embed);

    const int MT = (MTOK + 127) / 128;   // 1025

    // 2. A1 = relu(H @ W1 + b1) -> bf16 hi/lo
    ff_gemm<0><<<dim3(D2 / 128, MT), 256, GEMM_SMEM>>>(
        pHh, pHl, pW1h, pW1l, b1, nullptr, pA1h, pA1l, nullptr, MTOK, D2, D);

    // 3. X = A1 @ W2 + b2 + H  (fp32, into g_H)
    ff_gemm<1><<<dim3(D / 128, MT), 256, GEMM_SMEM>>>(
        pA1h, pA1l, pW2h, pW2l, b2, pH, nullptr, nullptr, pH, MTOK, D, D2);

    // 4. layernorm + gate + perturb
    ln_gate_kernel<<<MTOK, 128>>>(gamma, beta, Wg, bg, gumbel, temp);

    // 5. top-3 per batch row
    top3_kernel<<<BATCH, 256>>>();

    // 6. memory attention -> ctx
    attn_kernel<<<BATCH, 512>>>(Wr, br);

    // 7. out = ctx @ Wo + bo
    out_gemm<<<(VOCAB + 127) / 128, 128>>>(Wo, bo, out);
}

// round 4
// speedup vs baseline: 3.1991x; 1.1317x over previous
#include <cuda_runtime.h>
#include <cuda_bf16.h>
#include <math.h>
#include <cstdint>

// ---------------- problem constants ----------------
constexpr int BATCH = 64;
constexpr int TFULL = 2049;
constexpr int TCTX  = 2048;
constexpr int D     = 512;
constexpr int D2    = 1024;
constexpr int VOCAB = 50257;
constexpr int MTOK  = BATCH * TFULL;   // 131136

// ---------------- scratch (device globals) ----------------
__device__ float          g_H  [(size_t)MTOK * D];    // h, then x = h + ff
__device__ __nv_bfloat16  g_Hh [(size_t)MTOK * D];
__device__ __nv_bfloat16  g_Hl [(size_t)MTOK * D];
__device__ __nv_bfloat16  g_A1h[(size_t)MTOK * D2];
__device__ __nv_bfloat16  g_A1l[(size_t)MTOK * D2];
__device__ __nv_bfloat16  g_W1h[(size_t)D2 * D];      // W1^T split  [N=D2, K=D]
__device__ __nv_bfloat16  g_W1l[(size_t)D2 * D];
__device__ __nv_bfloat16  g_W2h[(size_t)D * D2];      // W2^T split  [N=D,  K=D2]
__device__ __nv_bfloat16  g_W2l[(size_t)D * D2];
__device__ float          g_HID[(size_t)MTOK * D];
__device__ float          g_PERT[BATCH * TCTX];
__device__ int            g_IDX [BATCH * 3];
__device__ float          g_CTX [BATCH * D];

// ---------------- PTX helpers (base-target features only) ----------------
__device__ __forceinline__ unsigned smem_u32(const void* p) {
    unsigned a;
    asm("{ .reg .u64 t; cvta.to.shared.u64 t, %1; cvt.u32.u64 %0, t; }" : "=r"(a) : "l"(p));
    return a;
}
__device__ __forceinline__ void cp16(unsigned dst, const void* src, int sz) {
    asm volatile("cp.async.cg.shared.global [%0], [%1], 16, %2;"
                 :: "r"(dst), "l"(src), "r"(sz) : "memory");
}
__device__ __forceinline__ void ldsm4(unsigned& r0, unsigned& r1, unsigned& r2, unsigned& r3,
                                      unsigned addr) {
    asm volatile("ldmatrix.sync.aligned.m8n8.x4.shared.b16 {%0,%1,%2,%3}, [%4];"
                 : "=r"(r0), "=r"(r1), "=r"(r2), "=r"(r3) : "r"(addr));
}
__device__ __forceinline__ void mma_bf16(float* c, const unsigned* a, const unsigned* b) {
    asm volatile("mma.sync.aligned.m16n8k16.row.col.f32.bf16.bf16.f32 "
                 "{%0,%1,%2,%3}, {%4,%5,%6,%7}, {%8,%9}, {%0,%1,%2,%3};"
                 : "+f"(c[0]), "+f"(c[1]), "+f"(c[2]), "+f"(c[3])
                 : "r"(a[0]), "r"(a[1]), "r"(a[2]), "r"(a[3]), "r"(b[0]), "r"(b[1]));
}
__device__ __forceinline__ void split_pack(float v0, float v1, unsigned& ph, unsigned& pl) {
    __nv_bfloat16 h0 = __float2bfloat16_rn(v0);
    __nv_bfloat16 h1 = __float2bfloat16_rn(v1);
    __nv_bfloat16 l0 = __float2bfloat16_rn(v0 - __bfloat162float(h0));
    __nv_bfloat16 l1 = __float2bfloat16_rn(v1 - __bfloat162float(h1));
    ph = (unsigned)__bfloat16_as_ushort(h0) | ((unsigned)__bfloat16_as_ushort(h1) << 16);
    pl = (unsigned)__bfloat16_as_ushort(l0) | ((unsigned)__bfloat16_as_ushort(l1) << 16);
}

// ---------------- weight prep: transpose + bf16 split ----------------
__global__ void wprep(const float* __restrict__ W,
                      __nv_bfloat16* __restrict__ Bh, __nv_bfloat16* __restrict__ Bl,
                      int K, int N)
{
    int i = blockIdx.x * 256 + threadIdx.x;
    if (i >= K * N) return;
    int k = i / N, n = i - k * N;
    float v = W[i];
    __nv_bfloat16 h = __float2bfloat16_rn(v);
    __nv_bfloat16 l = __float2bfloat16_rn(v - __bfloat162float(h));
    Bh[(size_t)n * K + k] = h;
    Bl[(size_t)n * K + k] = l;
}

// ---------------- gather: embed lookup + bf16 split ----------------
__global__ void gather_kernel(const int* __restrict__ seq, const float* __restrict__ embed)
{
    int m = blockIdx.x, tid = threadIdx.x;  // 128 threads, float4 each
    int tok = seq[m];
    float4 v = reinterpret_cast<const float4*>(embed + (size_t)tok * D)[tid];
    reinterpret_cast<float4*>(g_H + (size_t)m * D)[tid] = v;
    unsigned h0, l0, h1, l1;
    split_pack(v.x, v.y, h0, l0);
    split_pack(v.z, v.w, h1, l1);
    reinterpret_cast<uint2*>(g_Hh + (size_t)m * D)[tid] = make_uint2(h0, h1);
    reinterpret_cast<uint2*>(g_Hl + (size_t)m * D)[tid] = make_uint2(l0, l1);
}

// ---------------- mma.sync split-bf16 GEMM ----------------
// C = A @ B^T (+bias, epilogue). A: [M,K] bf16 hi/lo, B: [N,K] bf16 hi/lo.
// CTA tile 128x128, 8 warps (4 M x 2 N), warp tile 32x64, BK=32, 3-stage cp.async.
// Per-stage smem: Ah[2][128][16], Al, Bh, Bl  (each 8KB, 32KB/stage).
// Slice layout: elem (row, k) of slice s at  s*4096 + row*32 + (k%16)*2   (bytes).
constexpr int STAGE_BYTES = 32768;
constexpr int GEMM_SMEM   = 3 * STAGE_BYTES;   // 98304 -> two CTAs per SM

__device__ __forceinline__ void fill_stage(unsigned sb,
    const __nv_bfloat16* __restrict__ Ah, const __nv_bfloat16* __restrict__ Al,
    const __nv_bfloat16* __restrict__ Bh, const __nv_bfloat16* __restrict__ Bl,
    int K, int m0, int M, int n0, int kc, int tid)
{
    int m = tid >> 1, half = tid & 1;
    int arow = m0 + m;
    int asz  = (arow < M) ? 16 : 0;
    size_t aoff = (size_t)(asz ? arow : 0) * K + kc + half * 8;
    size_t boff = (size_t)(n0 + m) * K + kc + half * 8;
    unsigned dst = sb + m * 32 + half * 16;
    #pragma unroll
    for (int s = 0; s < 2; s++) {
        cp16(dst + s * 4096,         Ah + aoff + s * 16, asz);
        cp16(dst + 8192 + s * 4096,  Al + aoff + s * 16, asz);
        cp16(dst + 16384 + s * 4096, Bh + boff + s * 16, 16);
        cp16(dst + 24576 + s * 4096, Bl + boff + s * 16, 16);
    }
    asm volatile("cp.async.commit_group;" ::: "memory");
}

// MODE 0: relu + bf16 hi/lo split out.  MODE 1: + bias + addsrc, fp32 out.
template<int MODE>
__global__ __launch_bounds__(256, 2) void ff_gemm(
    const __nv_bfloat16* __restrict__ Ah, const __nv_bfloat16* __restrict__ Al,
    const __nv_bfloat16* __restrict__ Bh, const __nv_bfloat16* __restrict__ Bl,
    const float* __restrict__ bias, const float* __restrict__ addsrc,
    __nv_bfloat16* __restrict__ Ch, __nv_bfloat16* __restrict__ Cl,
    float* __restrict__ Cf, int M, int N, int K)
{
    extern __shared__ __align__(128) char smem[];
    unsigned sb = smem_u32(smem);
    const int tid = threadIdx.x, lane = tid & 31, wid = tid >> 5;
    const int wm = wid & 3, wn = wid >> 2;
    const int m0 = blockIdx.y * 128, n0 = blockIdx.x * 128;

    // per-lane ldmatrix offsets (within a k-slice)
    const unsigned aO = (unsigned)((wm * 32 + (lane & 15)) * 32 + (lane >> 4) * 16);
    const unsigned bO = 16384u +
        (unsigned)((wn * 64 + (lane >> 4) * 8 + (lane & 7)) * 32 + ((lane >> 3) & 1) * 16);

    float acc[2][8][4];
    #pragma unroll
    for (int i = 0; i < 2; i++)
        #pragma unroll
        for (int j = 0; j < 8; j++)
            #pragma unroll
            for (int q = 0; q < 4; q++) acc[i][j][q] = 0.f;

    const int NC = K >> 5;
    fill_stage(sb + 0 * STAGE_BYTES, Ah, Al, Bh, Bl, K, m0, M, n0, 0,  tid);
    fill_stage(sb + 1 * STAGE_BYTES, Ah, Al, Bh, Bl, K, m0, M, n0, 32, tid);

    int sidx = 0;   // stage index of iteration c (c % 3, tracked incrementally)
    for (int c = 0; c < NC; c++) {
        if (c + 1 < NC) asm volatile("cp.async.wait_group 1;" ::: "memory");
        else            asm volatile("cp.async.wait_group 0;" ::: "memory");
        __syncthreads();

        int pf = c + 2;
        if (pf < NC) {
            int psidx = sidx + 2; if (psidx >= 3) psidx -= 3;
            fill_stage(sb + psidx * STAGE_BYTES, Ah, Al, Bh, Bl, K, m0, M, n0, pf * 32, tid);
        }

        unsigned st = sb + sidx * STAGE_BYTES;
        #pragma unroll
        for (int ks = 0; ks < 2; ks++) {
            unsigned sl = st + ks * 4096;
            unsigned ah[2][4], al[2][4], bh[8][2], bl[8][2];
            #pragma unroll
            for (int mt = 0; mt < 2; mt++) {
                ldsm4(ah[mt][0], ah[mt][1], ah[mt][2], ah[mt][3], sl + aO + mt * 512);
                ldsm4(al[mt][0], al[mt][1], al[mt][2], al[mt][3], sl + 8192 + aO + mt * 512);
            }
            #pragma unroll
            for (int pr = 0; pr < 4; pr++) {
                ldsm4(bh[2*pr][0], bh[2*pr][1], bh[2*pr+1][0], bh[2*pr+1][1],
                      sl + bO + pr * 512);
                ldsm4(bl[2*pr][0], bl[2*pr][1], bl[2*pr+1][0], bl[2*pr+1][1],
                      sl + 8192 + bO + pr * 512);
            }
            #pragma unroll
            for (int mt = 0; mt < 2; mt++)
                #pragma unroll
                for (int nt = 0; nt < 8; nt++) {
                    mma_bf16(acc[mt][nt], ah[mt], bh[nt]);
                    mma_bf16(acc[mt][nt], al[mt], bh[nt]);
                    mma_bf16(acc[mt][nt], ah[mt], bl[nt]);
                }
        }
        if (++sidx == 3) sidx = 0;
    }

    // ---------------- epilogue ----------------
    const int g = lane >> 2, t4 = lane & 3;
    #pragma unroll
    for (int mt = 0; mt < 2; mt++) {
        int r0 = m0 + wm * 32 + mt * 16 + g;
        #pragma unroll
        for (int nt = 0; nt < 8; nt++) {
            int n = n0 + wn * 64 + nt * 8 + t4 * 2;
            float b0 = bias[n], b1 = bias[n + 1];
            if (MODE == 0) {
                if (r0 < M) {
                    float v0 = fmaxf(acc[mt][nt][0] + b0, 0.f);
                    float v1 = fmaxf(acc[mt][nt][1] + b1, 0.f);
                    unsigned ph, pl; split_pack(v0, v1, ph, pl);
                    *reinterpret_cast<unsigned*>(Ch + (size_t)r0 * N + n) = ph;
                    *reinterpret_cast<unsigned*>(Cl + (size_t)r0 * N + n) = pl;
                }
                if (r0 + 8 < M) {
                    float v0 = fmaxf(acc[mt][nt][2] + b0, 0.f);
                    float v1 = fmaxf(acc[mt][nt][3] + b1, 0.f);
                    unsigned ph, pl; split_pack(v0, v1, ph, pl);
                    *reinterpret_cast<unsigned*>(Ch + (size_t)(r0 + 8) * N + n) = ph;
                    *reinterpret_cast<unsigned*>(Cl + (size_t)(r0 + 8) * N + n) = pl;
                }
            } else {
                if (r0 < M) {
                    float2 a = *reinterpret_cast<const float2*>(addsrc + (size_t)r0 * N + n);
                    float2 o = make_float2(acc[mt][nt][0] + b0 + a.x,
                                           acc[mt][nt][1] + b1 + a.y);
                    *reinterpret_cast<float2*>(Cf + (size_t)r0 * N + n) = o;
                }
                if (r0 + 8 < M) {
                    float2 a = *reinterpret_cast<const float2*>(addsrc + (size_t)(r0 + 8) * N + n);
                    float2 o = make_float2(acc[mt][nt][2] + b0 + a.x,
                                           acc[mt][nt][3] + b1 + a.y);
                    *reinterpret_cast<float2*>(Cf + (size_t)(r0 + 8) * N + n) = o;
                }
            }
        }
    }
}

// ---------------- layernorm + gate + perturb ----------------
__global__ __launch_bounds__(128) void ln_gate_kernel(
    const float* __restrict__ gamma, const float* __restrict__ beta,
    const float* __restrict__ Wg, const float* __restrict__ bgp,
    const float* __restrict__ gumbel, const float* __restrict__ temp)
{
    int m = blockIdx.x, tid = threadIdx.x;   // 128 threads, float4 each
    float4 x = reinterpret_cast<const float4*>(g_H + (size_t)m * D)[tid];
    float s = x.x + x.y + x.z + x.w;
    float q = x.x*x.x + x.y*x.y + x.z*x.z + x.w*x.w;
    #pragma unroll
    for (int o = 16; o > 0; o >>= 1) {
        s += __shfl_down_sync(0xffffffffu, s, o);
        q += __shfl_down_sync(0xffffffffu, q, o);
    }
    __shared__ float sh[8];
    __shared__ float sg[4];
    int lane = tid & 31, w = tid >> 5;
    if (lane == 0) { sh[w] = s; sh[4 + w] = q; }
    __syncthreads();
    float S = sh[0] + sh[1] + sh[2] + sh[3];
    float Q = sh[4] + sh[5] + sh[6] + sh[7];
    float mu = S * (1.f / 512.f);
    float rs = rsqrtf(Q * (1.f / 512.f) - mu * mu + 1e-5f);
    float4 g4 = reinterpret_cast<const float4*>(gamma)[tid];
    float4 b4 = reinterpret_cast<const float4*>(beta)[tid];
    float4 h;
    h.x = (x.x - mu) * rs * g4.x + b4.x;
    h.y = (x.y - mu) * rs * g4.y + b4.y;
    h.z = (x.z - mu) * rs * g4.z + b4.z;
    h.w = (x.w - mu) * rs * g4.w + b4.w;
    reinterpret_cast<float4*>(g_HID + (size_t)m * D)[tid] = h;
    float4 wg = reinterpret_cast<const float4*>(Wg)[tid];
    float g = h.x*wg.x + h.y*wg.y + h.z*wg.z + h.w*wg.w;
    #pragma unroll
    for (int o = 16; o > 0; o >>= 1) g += __shfl_down_sync(0xffffffffu, g, o);
    if (lane == 0) sg[w] = g;
    __syncthreads();
    if (tid == 0) {
        float G = sg[0] + sg[1] + sg[2] + sg[3];
        int b = m / TFULL, t = m - b * TFULL;
        if (t < TCTX)
            g_PERT[b * TCTX + t] = (G + bgp[0] + gumbel[b * TCTX + t]) / temp[0];
    }
}

// ---------------- per-row top-3 ----------------
__global__ void top3_kernel()
{
    int b = blockIdx.x, tid = threadIdx.x;   // 256 threads
    float bv[3] = {-1e30f, -1e30f, -1e30f};
    int   bi[3] = {0, 0, 0};
    for (int t = tid; t < TCTX; t += 256) {
        float v = g_PERT[b * TCTX + t];
        if (v > bv[0]) { bv[2]=bv[1]; bi[2]=bi[1]; bv[1]=bv[0]; bi[1]=bi[0]; bv[0]=v; bi[0]=t; }
        else if (v > bv[1]) { bv[2]=bv[1]; bi[2]=bi[1]; bv[1]=v; bi[1]=t; }
        else if (v > bv[2]) { bv[2]=v; bi[2]=t; }
    }
    __shared__ float sv[768];
    __shared__ int   si[768];
    sv[tid*3+0]=bv[0]; sv[tid*3+1]=bv[1]; sv[tid*3+2]=bv[2];
    si[tid*3+0]=bi[0]; si[tid*3+1]=bi[1]; si[tid*3+2]=bi[2];
    __syncthreads();
    if (tid == 0) {
        float rv[3] = {-1e30f, -1e30f, -1e30f};
        int   ri[3] = {0, 0, 0};
        for (int e = 0; e < 768; e++) {
            float v = sv[e]; int i = si[e];
            if (v > rv[0]) { rv[2]=rv[1]; ri[2]=ri[1]; rv[1]=rv[0]; ri[1]=ri[0]; rv[0]=v; ri[0]=i; }
            else if (v > rv[1]) { rv[2]=rv[1]; ri[2]=ri[1]; rv[1]=v; ri[1]=i; }
            else if (v > rv[2]) { rv[2]=v; ri[2]=i; }
        }
        g_IDX[b*3+0]=ri[0]; g_IDX[b*3+1]=ri[1]; g_IDX[b*3+2]=ri[2];
    }
}

// ---------------- memory attention ----------------
__global__ __launch_bounds__(512) void attn_kernel(
    const float* __restrict__ Wr, const float* __restrict__ br)
{
    int b = blockIdx.x, tid = threadIdx.x;   // 512 threads (one per d)
    __shared__ float hlast[D];
    __shared__ float gh[3][D];
    __shared__ float red[48];
    __shared__ float s_attn[3];
    size_t base = (size_t)b * TFULL * D;
    hlast[tid] = g_HID[base + (size_t)TCTX * D + tid];
    int i0 = g_IDX[b*3+0], i1 = g_IDX[b*3+1], i2 = g_IDX[b*3+2];
    gh[0][tid] = g_HID[base + (size_t)i0 * D + tid];
    gh[1][tid] = g_HID[base + (size_t)i1 * D + tid];
    gh[2][tid] = g_HID[base + (size_t)i2 * D + tid];
    __syncthreads();

    float qv = br[tid];
    #pragma unroll 4
    for (int j = 0; j < D; j++)
        qv += hlast[j] * Wr[(size_t)j * D + tid];

    float p0 = gh[0][tid] * qv, p1 = gh[1][tid] * qv, p2 = gh[2][tid] * qv;
    #pragma unroll
    for (int o = 16; o > 0; o >>= 1) {
        p0 += __shfl_down_sync(0xffffffffu, p0, o);
        p1 += __shfl_down_sync(0xffffffffu, p1, o);
        p2 += __shfl_down_sync(0xffffffffu, p2, o);
    }
    int lane = tid & 31, w = tid >> 5;
    if (lane == 0) { red[w] = p0; red[16 + w] = p1; red[32 + w] = p2; }
    __syncthreads();
    if (tid == 0) {
        float s0 = 0.f, s1 = 0.f, s2 = 0.f;
        for (int i = 0; i < 16; i++) { s0 += red[i]; s1 += red[16+i]; s2 += red[32+i]; }
        float mx = fmaxf(fmaxf(s0, s1), fmaxf(s2, 0.f));
        float e0 = expf(s0 - mx), e1 = expf(s1 - mx), e2 = expf(s2 - mx);
        float den = e0 + e1 + e2 + 13.f * expf(-mx);
        s_attn[0] = e0 / den; s_attn[1] = e1 / den; s_attn[2] = e2 / den;
    }
    __syncthreads();
    g_CTX[b * D + tid] = s_attn[0]*gh[0][tid] + s_attn[1]*gh[1][tid] + s_attn[2]*gh[2][tid];
}

// ---------------- out = ctx @ Wo + bo  (64 x 50257, K=512), Wo read ONCE ----------------
// 256 threads: thread owns column n = blk*128 + (tid&127), rows rh*32..rh*32+31.
// ctx staged in smem in 64-wide K chunks; inner loop = 1 Wo load + 32 FMA.
__global__ __launch_bounds__(256) void out_gemm(
    const float* __restrict__ Wo, const float* __restrict__ bo,
    float* __restrict__ out)
{
    __shared__ float sc[64 * 64];            // 64 rows x 64 k-chunk
    int tid = threadIdx.x;
    int n  = blockIdx.x * 128 + (tid & 127);
    int rh = tid >> 7;                       // 0 or 1 -> rows [0,32) or [32,64)
    bool valid = (n < VOCAB);

    float acc[32];
    #pragma unroll
    for (int r = 0; r < 32; r++) acc[r] = 0.f;

    for (int k0 = 0; k0 < 512; k0 += 64) {
        __syncthreads();
        #pragma unroll
        for (int i = tid; i < 64 * 64; i += 256) {
            int row = i >> 6, k = i & 63;
            sc[i] = g_CTX[row * 512 + k0 + k];
        }
        __syncthreads();
        if (valid) {
            const float* scr = sc + rh * 32 * 64;
            #pragma unroll 4
            for (int k = 0; k < 64; k++) {
                float w = Wo[(size_t)(k0 + k) * VOCAB + n];
                #pragma unroll
                for (int r = 0; r < 32; r++)
                    acc[r] += scr[r * 64 + k] * w;
            }
        }
    }
    if (valid) {
        float b = bo[n];
        #pragma unroll
        for (int r = 0; r < 32; r++)
            out[(size_t)(rh * 32 + r) * VOCAB + n] = acc[r] + b;
    }
}

// ---------------- launch ----------------
extern "C" void kernel_launch(void* const* d_in, const int* in_sizes, int n_in,
                              void* d_out, int out_size)
{
    const int*   seq    = (const int*)  d_in[0];
    const float* temp   = (const float*)d_in[1];
    const float* gumbel = (const float*)d_in[2];
    const float* embed  = (const float*)d_in[3];
    const float* W1     = (const float*)d_in[4];
    const float* b1     = (const float*)d_in[5];
    const float* W2     = (const float*)d_in[6];
    const float* b2     = (const float*)d_in[7];
    const float* gamma  = (const float*)d_in[8];
    const float* beta   = (const float*)d_in[9];
    const float* Wg     = (const float*)d_in[10];
    const float* bg     = (const float*)d_in[11];
    const float* Wr     = (const float*)d_in[12];
    const float* br     = (const float*)d_in[13];
    const float* Wo     = (const float*)d_in[14];
    const float* bo     = (const float*)d_in[15];
    float* out = (float*)d_out;

    float *pH;
    __nv_bfloat16 *pHh, *pHl, *pA1h, *pA1l, *pW1h, *pW1l, *pW2h, *pW2l;
    cudaGetSymbolAddress((void**)&pH,   g_H);
    cudaGetSymbolAddress((void**)&pHh,  g_Hh);
    cudaGetSymbolAddress((void**)&pHl,  g_Hl);
    cudaGetSymbolAddress((void**)&pA1h, g_A1h);
    cudaGetSymbolAddress((void**)&pA1l, g_A1l);
    cudaGetSymbolAddress((void**)&pW1h, g_W1h);
    cudaGetSymbolAddress((void**)&pW1l, g_W1l);
    cudaGetSymbolAddress((void**)&pW2h, g_W2h);
    cudaGetSymbolAddress((void**)&pW2l, g_W2l);

    cudaFuncSetAttribute(ff_gemm<0>, cudaFuncAttributeMaxDynamicSharedMemorySize, GEMM_SMEM);
    cudaFuncSetAttribute(ff_gemm<1>, cudaFuncAttributeMaxDynamicSharedMemorySize, GEMM_SMEM);

    // 0. weight prep (transpose + split)
    wprep<<<(D * D2 + 255) / 256, 256>>>(W1, pW1h, pW1l, D, D2);
    wprep<<<(D2 * D + 255) / 256, 256>>>(W2, pW2h, pW2l, D2, D);

    // 1. gather embeddings (+ split)
    gather_kernel<<<MTOK, 128>>>(seq, embed);

    const int MT = (MTOK + 127) / 128;   // 1025

    // 2. A1 = relu(H @ W1 + b1) -> bf16 hi/lo
    ff_gemm<0><<<dim3(D2 / 128, MT), 256, GEMM_SMEM>>>(
        pHh, pHl, pW1h, pW1l, b1, nullptr, pA1h, pA1l, nullptr, MTOK, D2, D);

    // 3. X = A1 @ W2 + b2 + H  (fp32, into g_H)
    ff_gemm<1><<<dim3(D / 128, MT), 256, GEMM_SMEM>>>(
        pA1h, pA1l, pW2h, pW2l, b2, pH, nullptr, nullptr, pH, MTOK, D, D2);

    // 4. layernorm + gate + perturb
    ln_gate_kernel<<<MTOK, 128>>>(gamma, beta, Wg, bg, gumbel, temp);

    // 5. top-3 per batch row
    top3_kernel<<<BATCH, 256>>>();

    // 6. memory attention -> ctx
    attn_kernel<<<BATCH, 512>>>(Wr, br);

    // 7. out = ctx @ Wo + bo
    out_gemm<<<(VOCAB + 127) / 128, 256>>>(Wo, bo, out);
}

// round 5
// speedup vs baseline: 3.2804x; 1.0254x over previous
#include <cuda_runtime.h>
#include <cuda_bf16.h>
#include <math.h>
#include <cstdint>

// ---------------- problem constants ----------------
constexpr int BATCH = 64;
constexpr int TFULL = 2049;
constexpr int TCTX  = 2048;
constexpr int D     = 512;
constexpr int D2    = 1024;
constexpr int VOCAB = 50257;
constexpr int MTOK  = BATCH * TFULL;   // 131136

// ---------------- scratch (device globals) ----------------
__device__ float          g_H  [(size_t)MTOK * D];    // h, then x = h + ff
__device__ __nv_bfloat16  g_Hh [(size_t)MTOK * D];
__device__ __nv_bfloat16  g_Hl [(size_t)MTOK * D];
__device__ __nv_bfloat16  g_A1h[(size_t)MTOK * D2];
__device__ __nv_bfloat16  g_A1l[(size_t)MTOK * D2];
__device__ __nv_bfloat16  g_W1h[(size_t)D2 * D];      // W1^T split  [N=D2, K=D]
__device__ __nv_bfloat16  g_W1l[(size_t)D2 * D];
__device__ __nv_bfloat16  g_W2h[(size_t)D * D2];      // W2^T split  [N=D,  K=D2]
__device__ __nv_bfloat16  g_W2l[(size_t)D * D2];
__device__ float          g_HID[(size_t)MTOK * D];
__device__ float          g_PERT[BATCH * TCTX];
__device__ int            g_IDX [BATCH * 3];
__device__ float          g_CTX [BATCH * D];

// ---------------- PTX helpers (base-target features only) ----------------
__device__ __forceinline__ unsigned smem_u32(const void* p) {
    unsigned a;
    asm("{ .reg .u64 t; cvta.to.shared.u64 t, %1; cvt.u32.u64 %0, t; }" : "=r"(a) : "l"(p));
    return a;
}
__device__ __forceinline__ void cp16(unsigned dst, const void* src, int sz) {
    asm volatile("cp.async.cg.shared.global [%0], [%1], 16, %2;"
                 :: "r"(dst), "l"(src), "r"(sz) : "memory");
}
__device__ __forceinline__ void ldsm4(unsigned& r0, unsigned& r1, unsigned& r2, unsigned& r3,
                                      unsigned addr) {
    asm volatile("ldmatrix.sync.aligned.m8n8.x4.shared.b16 {%0,%1,%2,%3}, [%4];"
                 : "=r"(r0), "=r"(r1), "=r"(r2), "=r"(r3) : "r"(addr));
}
__device__ __forceinline__ void mma_bf16(float* c, const unsigned* a, const unsigned* b) {
    asm volatile("mma.sync.aligned.m16n8k16.row.col.f32.bf16.bf16.f32 "
                 "{%0,%1,%2,%3}, {%4,%5,%6,%7}, {%8,%9}, {%0,%1,%2,%3};"
                 : "+f"(c[0]), "+f"(c[1]), "+f"(c[2]), "+f"(c[3])
                 : "r"(a[0]), "r"(a[1]), "r"(a[2]), "r"(a[3]), "r"(b[0]), "r"(b[1]));
}
__device__ __forceinline__ void split_pack(float v0, float v1, unsigned& ph, unsigned& pl) {
    __nv_bfloat16 h0 = __float2bfloat16_rn(v0);
    __nv_bfloat16 h1 = __float2bfloat16_rn(v1);
    __nv_bfloat16 l0 = __float2bfloat16_rn(v0 - __bfloat162float(h0));
    __nv_bfloat16 l1 = __float2bfloat16_rn(v1 - __bfloat162float(h1));
    ph = (unsigned)__bfloat16_as_ushort(h0) | ((unsigned)__bfloat16_as_ushort(h1) << 16);
    pl = (unsigned)__bfloat16_as_ushort(l0) | ((unsigned)__bfloat16_as_ushort(l1) << 16);
}

// ---------------- weight prep: transpose + bf16 split ----------------
__global__ void wprep(const float* __restrict__ W,
                      __nv_bfloat16* __restrict__ Bh, __nv_bfloat16* __restrict__ Bl,
                      int K, int N)
{
    int i = blockIdx.x * 256 + threadIdx.x;
    if (i >= K * N) return;
    int k = i / N, n = i - k * N;
    float v = W[i];
    __nv_bfloat16 h = __float2bfloat16_rn(v);
    __nv_bfloat16 l = __float2bfloat16_rn(v - __bfloat162float(h));
    Bh[(size_t)n * K + k] = h;
    Bl[(size_t)n * K + k] = l;
}

// ---------------- gather: warp-per-row embed lookup + bf16 split ----------------
__global__ __launch_bounds__(256) void gather_kernel(const int* __restrict__ seq,
                                                     const float* __restrict__ embed)
{
    int w = threadIdx.x >> 5, lane = threadIdx.x & 31;
    int m = blockIdx.x * 8 + w;             // MTOK divisible by 8
    int tok = seq[m];
    const float4* src = reinterpret_cast<const float4*>(embed + (size_t)tok * D);
    float4* dstH = reinterpret_cast<float4*>(g_H + (size_t)m * D);
    uint2* dstHh = reinterpret_cast<uint2*>(g_Hh + (size_t)m * D);
    uint2* dstHl = reinterpret_cast<uint2*>(g_Hl + (size_t)m * D);
    #pragma unroll
    for (int i = 0; i < 4; i++) {
        int j = lane + 32 * i;
        float4 v = src[j];
        dstH[j] = v;
        unsigned h0, l0, h1, l1;
        split_pack(v.x, v.y, h0, l0);
        split_pack(v.z, v.w, h1, l1);
        dstHh[j] = make_uint2(h0, h1);
        dstHl[j] = make_uint2(l0, l1);
    }
}

// ---------------- mma.sync split-bf16 GEMM ----------------
// C = A @ B^T (+bias, epilogue). A: [M,K] bf16 hi/lo, B: [N,K] bf16 hi/lo.
// CTA tile 128x128, 8 warps (4 M x 2 N), warp tile 32x64, BK=32, 3-stage cp.async.
// Per-stage smem: Ah[2][128][16], Al, Bh, Bl  (each 8KB, 32KB/stage).
// Slice layout: elem (row, k) of slice s at  s*4096 + row*32 + (k%16)*2   (bytes).
constexpr int STAGE_BYTES = 32768;
constexpr int GEMM_SMEM   = 3 * STAGE_BYTES;   // 98304 -> two CTAs per SM

__device__ __forceinline__ void fill_stage(unsigned sb,
    const __nv_bfloat16* __restrict__ Ah, const __nv_bfloat16* __restrict__ Al,
    const __nv_bfloat16* __restrict__ Bh, const __nv_bfloat16* __restrict__ Bl,
    int K, int m0, int M, int n0, int kc, int tid)
{
    int m = tid >> 1, half = tid & 1;
    int arow = m0 + m;
    int asz  = (arow < M) ? 16 : 0;
    size_t aoff = (size_t)(asz ? arow : 0) * K + kc + half * 8;
    size_t boff = (size_t)(n0 + m) * K + kc + half * 8;
    unsigned dst = sb + m * 32 + half * 16;
    #pragma unroll
    for (int s = 0; s < 2; s++) {
        cp16(dst + s * 4096,         Ah + aoff + s * 16, asz);
        cp16(dst + 8192 + s * 4096,  Al + aoff + s * 16, asz);
        cp16(dst + 16384 + s * 4096, Bh + boff + s * 16, 16);
        cp16(dst + 24576 + s * 4096, Bl + boff + s * 16, 16);
    }
    asm volatile("cp.async.commit_group;" ::: "memory");
}

// MODE 0: relu + bf16 hi/lo split out.  MODE 1: + bias + addsrc, fp32 out.
template<int MODE>
__global__ __launch_bounds__(256, 2) void ff_gemm(
    const __nv_bfloat16* __restrict__ Ah, const __nv_bfloat16* __restrict__ Al,
    const __nv_bfloat16* __restrict__ Bh, const __nv_bfloat16* __restrict__ Bl,
    const float* __restrict__ bias, const float* __restrict__ addsrc,
    __nv_bfloat16* __restrict__ Ch, __nv_bfloat16* __restrict__ Cl,
    float* __restrict__ Cf, int M, int N, int K)
{
    extern __shared__ __align__(128) char smem[];
    unsigned sb = smem_u32(smem);
    const int tid = threadIdx.x, lane = tid & 31, wid = tid >> 5;
    const int wm = wid & 3, wn = wid >> 2;
    const int m0 = blockIdx.y * 128, n0 = blockIdx.x * 128;

    // per-lane ldmatrix offsets (within a k-slice)
    const unsigned aO = (unsigned)((wm * 32 + (lane & 15)) * 32 + (lane >> 4) * 16);
    const unsigned bO = 16384u +
        (unsigned)((wn * 64 + (lane >> 4) * 8 + (lane & 7)) * 32 + ((lane >> 3) & 1) * 16);

    float acc[2][8][4];
    #pragma unroll
    for (int i = 0; i < 2; i++)
        #pragma unroll
        for (int j = 0; j < 8; j++)
            #pragma unroll
            for (int q = 0; q < 4; q++) acc[i][j][q] = 0.f;

    const int NC = K >> 5;
    fill_stage(sb + 0 * STAGE_BYTES, Ah, Al, Bh, Bl, K, m0, M, n0, 0,  tid);
    fill_stage(sb + 1 * STAGE_BYTES, Ah, Al, Bh, Bl, K, m0, M, n0, 32, tid);

    int sidx = 0;   // stage index of iteration c (c % 3, tracked incrementally)
    for (int c = 0; c < NC; c++) {
        if (c + 1 < NC) asm volatile("cp.async.wait_group 1;" ::: "memory");
        else            asm volatile("cp.async.wait_group 0;" ::: "memory");
        __syncthreads();

        int pf = c + 2;
        if (pf < NC) {
            int psidx = sidx + 2; if (psidx >= 3) psidx -= 3;
            fill_stage(sb + psidx * STAGE_BYTES, Ah, Al, Bh, Bl, K, m0, M, n0, pf * 32, tid);
        }

        unsigned st = sb + sidx * STAGE_BYTES;
        #pragma unroll
        for (int ks = 0; ks < 2; ks++) {
            unsigned sl = st + ks * 4096;
            unsigned ah[2][4], al[2][4], bh[8][2], bl[8][2];
            #pragma unroll
            for (int mt = 0; mt < 2; mt++) {
                ldsm4(ah[mt][0], ah[mt][1], ah[mt][2], ah[mt][3], sl + aO + mt * 512);
                ldsm4(al[mt][0], al[mt][1], al[mt][2], al[mt][3], sl + 8192 + aO + mt * 512);
            }
            #pragma unroll
            for (int pr = 0; pr < 4; pr++) {
                ldsm4(bh[2*pr][0], bh[2*pr][1], bh[2*pr+1][0], bh[2*pr+1][1],
                      sl + bO + pr * 512);
                ldsm4(bl[2*pr][0], bl[2*pr][1], bl[2*pr+1][0], bl[2*pr+1][1],
                      sl + 8192 + bO + pr * 512);
            }
            // pass-outer ordering: 16 independent accumulators between reuses
            // of the same acc -> no HMMA RAW chains.
            #pragma unroll
            for (int mt = 0; mt < 2; mt++)
                #pragma unroll
                for (int nt = 0; nt < 8; nt++)
                    mma_bf16(acc[mt][nt], ah[mt], bh[nt]);
            #pragma unroll
            for (int mt = 0; mt < 2; mt++)
                #pragma unroll
                for (int nt = 0; nt < 8; nt++)
                    mma_bf16(acc[mt][nt], al[mt], bh[nt]);
            #pragma unroll
            for (int mt = 0; mt < 2; mt++)
                #pragma unroll
                for (int nt = 0; nt < 8; nt++)
                    mma_bf16(acc[mt][nt], ah[mt], bl[nt]);
        }
        if (++sidx == 3) sidx = 0;
    }

    // ---------------- epilogue ----------------
    const int g = lane >> 2, t4 = lane & 3;
    #pragma unroll
    for (int mt = 0; mt < 2; mt++) {
        int r0 = m0 + wm * 32 + mt * 16 + g;
        #pragma unroll
        for (int nt = 0; nt < 8; nt++) {
            int n = n0 + wn * 64 + nt * 8 + t4 * 2;
            float b0 = bias[n], b1 = bias[n + 1];
            if (MODE == 0) {
                if (r0 < M) {
                    float v0 = fmaxf(acc[mt][nt][0] + b0, 0.f);
                    float v1 = fmaxf(acc[mt][nt][1] + b1, 0.f);
                    unsigned ph, pl; split_pack(v0, v1, ph, pl);
                    *reinterpret_cast<unsigned*>(Ch + (size_t)r0 * N + n) = ph;
                    *reinterpret_cast<unsigned*>(Cl + (size_t)r0 * N + n) = pl;
                }
                if (r0 + 8 < M) {
                    float v0 = fmaxf(acc[mt][nt][2] + b0, 0.f);
                    float v1 = fmaxf(acc[mt][nt][3] + b1, 0.f);
                    unsigned ph, pl; split_pack(v0, v1, ph, pl);
                    *reinterpret_cast<unsigned*>(Ch + (size_t)(r0 + 8) * N + n) = ph;
                    *reinterpret_cast<unsigned*>(Cl + (size_t)(r0 + 8) * N + n) = pl;
                }
            } else {
                if (r0 < M) {
                    float2 a = *reinterpret_cast<const float2*>(addsrc + (size_t)r0 * N + n);
                    float2 o = make_float2(acc[mt][nt][0] + b0 + a.x,
                                           acc[mt][nt][1] + b1 + a.y);
                    *reinterpret_cast<float2*>(Cf + (size_t)r0 * N + n) = o;
                }
                if (r0 + 8 < M) {
                    float2 a = *reinterpret_cast<const float2*>(addsrc + (size_t)(r0 + 8) * N + n);
                    float2 o = make_float2(acc[mt][nt][2] + b0 + a.x,
                                           acc[mt][nt][3] + b1 + a.y);
                    *reinterpret_cast<float2*>(Cf + (size_t)(r0 + 8) * N + n) = o;
                }
            }
        }
    }
}

// ---------------- layernorm + gate + perturb (warp-per-row) ----------------
__global__ __launch_bounds__(256) void ln_gate_kernel(
    const float* __restrict__ gamma, const float* __restrict__ beta,
    const float* __restrict__ Wg, const float* __restrict__ bgp,
    const float* __restrict__ gumbel, const float* __restrict__ temp)
{
    int w = threadIdx.x >> 5, lane = threadIdx.x & 31;
    int m = blockIdx.x * 8 + w;             // MTOK divisible by 8
    const float4* x4 = reinterpret_cast<const float4*>(g_H + (size_t)m * D);
    const float4* g4 = reinterpret_cast<const float4*>(gamma);
    const float4* b4 = reinterpret_cast<const float4*>(beta);
    const float4* w4 = reinterpret_cast<const float4*>(Wg);
    float4* hid4 = reinterpret_cast<float4*>(g_HID + (size_t)m * D);

    float4 xv[4];
    float s = 0.f, q = 0.f;
    #pragma unroll
    for (int i = 0; i < 4; i++) {
        float4 v = x4[lane + 32 * i];
        xv[i] = v;
        s += v.x + v.y + v.z + v.w;
        q += v.x*v.x + v.y*v.y + v.z*v.z + v.w*v.w;
    }
    #pragma unroll
    for (int o = 16; o > 0; o >>= 1) {
        s += __shfl_xor_sync(0xffffffffu, s, o);
        q += __shfl_xor_sync(0xffffffffu, q, o);
    }
    float mu = s * (1.f / 512.f);
    float rs = rsqrtf(q * (1.f / 512.f) - mu * mu + 1e-5f);

    float gsum = 0.f;
    #pragma unroll
    for (int i = 0; i < 4; i++) {
        int j = lane + 32 * i;
        float4 gm = g4[j], bt = b4[j], wg = w4[j], v = xv[i];
        float4 h;
        h.x = (v.x - mu) * rs * gm.x + bt.x;
        h.y = (v.y - mu) * rs * gm.y + bt.y;
        h.z = (v.z - mu) * rs * gm.z + bt.z;
        h.w = (v.w - mu) * rs * gm.w + bt.w;
        hid4[j] = h;
        gsum += h.x*wg.x + h.y*wg.y + h.z*wg.z + h.w*wg.w;
    }
    #pragma unroll
    for (int o = 16; o > 0; o >>= 1)
        gsum += __shfl_xor_sync(0xffffffffu, gsum, o);
    if (lane == 0) {
        int b = m / TFULL, t = m - b * TFULL;
        if (t < TCTX)
            g_PERT[b * TCTX + t] = (gsum + bgp[0] + gumbel[b * TCTX + t]) / temp[0];
    }
}

// ---------------- per-row top-3 ----------------
__global__ void top3_kernel()
{
    int b = blockIdx.x, tid = threadIdx.x;   // 256 threads
    float bv[3] = {-1e30f, -1e30f, -1e30f};
    int   bi[3] = {0, 0, 0};
    for (int t = tid; t < TCTX; t += 256) {
        float v = g_PERT[b * TCTX + t];
        if (v > bv[0]) { bv[2]=bv[1]; bi[2]=bi[1]; bv[1]=bv[0]; bi[1]=bi[0]; bv[0]=v; bi[0]=t; }
        else if (v > bv[1]) { bv[2]=bv[1]; bi[2]=bi[1]; bv[1]=v; bi[1]=t; }
        else if (v > bv[2]) { bv[2]=v; bi[2]=t; }
    }
    __shared__ float sv[768];
    __shared__ int   si[768];
    sv[tid*3+0]=bv[0]; sv[tid*3+1]=bv[1]; sv[tid*3+2]=bv[2];
    si[tid*3+0]=bi[0]; si[tid*3+1]=bi[1]; si[tid*3+2]=bi[2];
    __syncthreads();
    if (tid == 0) {
        float rv[3] = {-1e30f, -1e30f, -1e30f};
        int   ri[3] = {0, 0, 0};
        for (int e = 0; e < 768; e++) {
            float v = sv[e]; int i = si[e];
            if (v > rv[0]) { rv[2]=rv[1]; ri[2]=ri[1]; rv[1]=rv[0]; ri[1]=ri[0]; rv[0]=v; ri[0]=i; }
            else if (v > rv[1]) { rv[2]=rv[1]; ri[2]=ri[1]; rv[1]=v; ri[1]=i; }
            else if (v > rv[2]) { rv[2]=v; ri[2]=i; }
        }
        g_IDX[b*3+0]=ri[0]; g_IDX[b*3+1]=ri[1]; g_IDX[b*3+2]=ri[2];
    }
}

// ---------------- memory attention ----------------
__global__ __launch_bounds__(512) void attn_kernel(
    const float* __restrict__ Wr, const float* __restrict__ br)
{
    int b = blockIdx.x, tid = threadIdx.x;   // 512 threads (one per d)
    __shared__ float hlast[D];
    __shared__ float gh[3][D];
    __shared__ float red[48];
    __shared__ float s_attn[3];
    size_t base = (size_t)b * TFULL * D;
    hlast[tid] = g_HID[base + (size_t)TCTX * D + tid];
    int i0 = g_IDX[b*3+0], i1 = g_IDX[b*3+1], i2 = g_IDX[b*3+2];
    gh[0][tid] = g_HID[base + (size_t)i0 * D + tid];
    gh[1][tid] = g_HID[base + (size_t)i1 * D + tid];
    gh[2][tid] = g_HID[base + (size_t)i2 * D + tid];
    __syncthreads();

    float qv = br[tid];
    #pragma unroll 4
    for (int j = 0; j < D; j++)
        qv += hlast[j] * Wr[(size_t)j * D + tid];

    float p0 = gh[0][tid] * qv, p1 = gh[1][tid] * qv, p2 = gh[2][tid] * qv;
    #pragma unroll
    for (int o = 16; o > 0; o >>= 1) {
        p0 += __shfl_down_sync(0xffffffffu, p0, o);
        p1 += __shfl_down_sync(0xffffffffu, p1, o);
        p2 += __shfl_down_sync(0xffffffffu, p2, o);
    }
    int lane = tid & 31, w = tid >> 5;
    if (lane == 0) { red[w] = p0; red[16 + w] = p1; red[32 + w] = p2; }
    __syncthreads();
    if (tid == 0) {
        float s0 = 0.f, s1 = 0.f, s2 = 0.f;
        for (int i = 0; i < 16; i++) { s0 += red[i]; s1 += red[16+i]; s2 += red[32+i]; }
        float mx = fmaxf(fmaxf(s0, s1), fmaxf(s2, 0.f));
        float e0 = expf(s0 - mx), e1 = expf(s1 - mx), e2 = expf(s2 - mx);
        float den = e0 + e1 + e2 + 13.f * expf(-mx);
        s_attn[0] = e0 / den; s_attn[1] = e1 / den; s_attn[2] = e2 / den;
    }
    __syncthreads();
    g_CTX[b * D + tid] = s_attn[0]*gh[0][tid] + s_attn[1]*gh[1][tid] + s_attn[2]*gh[2][tid];
}

// ---------------- out = ctx @ Wo + bo  (64 x 50257, K=512), Wo read ONCE ----------------
__global__ __launch_bounds__(256) void out_gemm(
    const float* __restrict__ Wo, const float* __restrict__ bo,
    float* __restrict__ out)
{
    __shared__ float sc[64 * 64];            // 64 rows x 64 k-chunk
    int tid = threadIdx.x;
    int n  = blockIdx.x * 128 + (tid & 127);
    int rh = tid >> 7;                       // 0 or 1 -> rows [0,32) or [32,64)
    bool valid = (n < VOCAB);

    float acc[32];
    #pragma unroll
    for (int r = 0; r < 32; r++) acc[r] = 0.f;

    for (int k0 = 0; k0 < 512; k0 += 64) {
        __syncthreads();
        #pragma unroll
        for (int i = tid; i < 64 * 64; i += 256) {
            int row = i >> 6, k = i & 63;
            sc[i] = g_CTX[row * 512 + k0 + k];
        }
        __syncthreads();
        if (valid) {
            const float* scr = sc + rh * 32 * 64;
            #pragma unroll 4
            for (int k = 0; k < 64; k++) {
                float w = Wo[(size_t)(k0 + k) * VOCAB + n];
                #pragma unroll
                for (int r = 0; r < 32; r++)
                    acc[r] += scr[r * 64 + k] * w;
            }
        }
    }
    if (valid) {
        float b = bo[n];
        #pragma unroll
        for (int r = 0; r < 32; r++)
            out[(size_t)(rh * 32 + r) * VOCAB + n] = acc[r] + b;
    }
}

// ---------------- launch ----------------
extern "C" void kernel_launch(void* const* d_in, const int* in_sizes, int n_in,
                              void* d_out, int out_size)
{
    const int*   seq    = (const int*)  d_in[0];
    const float* temp   = (const float*)d_in[1];
    const float* gumbel = (const float*)d_in[2];
    const float* embed  = (const float*)d_in[3];
    const float* W1     = (const float*)d_in[4];
    const float* b1     = (const float*)d_in[5];
    const float* W2     = (const float*)d_in[6];
    const float* b2     = (const float*)d_in[7];
    const float* gamma  = (const float*)d_in[8];
    const float* beta   = (const float*)d_in[9];
    const float* Wg     = (const float*)d_in[10];
    const float* bg     = (const float*)d_in[11];
    const float* Wr     = (const float*)d_in[12];
    const float* br     = (const float*)d_in[13];
    const float* Wo     = (const float*)d_in[14];
    const float* bo     = (const float*)d_in[15];
    float* out = (float*)d_out;

    float *pH;
    __nv_bfloat16 *pHh, *pHl, *pA1h, *pA1l, *pW1h, *pW1l, *pW2h, *pW2l;
    cudaGetSymbolAddress((void**)&pH,   g_H);
    cudaGetSymbolAddress((void**)&pHh,  g_Hh);
    cudaGetSymbolAddress((void**)&pHl,  g_Hl);
    cudaGetSymbolAddress((void**)&pA1h, g_A1h);
    cudaGetSymbolAddress((void**)&pA1l, g_A1l);
    cudaGetSymbolAddress((void**)&pW1h, g_W1h);
    cudaGetSymbolAddress((void**)&pW1l, g_W1l);
    cudaGetSymbolAddress((void**)&pW2h, g_W2h);
    cudaGetSymbolAddress((void**)&pW2l, g_W2l);

    cudaFuncSetAttribute(ff_gemm<0>, cudaFuncAttributeMaxDynamicSharedMemorySize, GEMM_SMEM);
    cudaFuncSetAttribute(ff_gemm<1>, cudaFuncAttributeMaxDynamicSharedMemorySize, GEMM_SMEM);

    // 0. weight prep (transpose + split)
    wprep<<<(D * D2 + 255) / 256, 256>>>(W1, pW1h, pW1l, D, D2);
    wprep<<<(D2 * D + 255) / 256, 256>>>(W2, pW2h, pW2l, D2, D);

    // 1. gather embeddings (+ split), warp per row
    gather_kernel<<<MTOK / 8, 256>>>(seq, embed);

    const int MT = (MTOK + 127) / 128;   // 1025

    // 2. A1 = relu(H @ W1 + b1) -> bf16 hi/lo
    ff_gemm<0><<<dim3(D2 / 128, MT), 256, GEMM_SMEM>>>(
        pHh, pHl, pW1h, pW1l, b1, nullptr, pA1h, pA1l, nullptr, MTOK, D2, D);

    // 3. X = A1 @ W2 + b2 + H  (fp32, into g_H)
    ff_gemm<1><<<dim3(D / 128, MT), 256, GEMM_SMEM>>>(
        pA1h, pA1l, pW2h, pW2l, b2, pH, nullptr, nullptr, pH, MTOK, D, D2);

    // 4. layernorm + gate + perturb, warp per row
    ln_gate_kernel<<<MTOK / 8, 256>>>(gamma, beta, Wg, bg, gumbel, temp);

    // 5. top-3 per batch row
    top3_kernel<<<BATCH, 256>>>();

    // 6. memory attention -> ctx
    attn_kernel<<<BATCH, 512>>>(Wr, br);

    // 7. out = ctx @ Wo + bo
    out_gemm<<<(VOCAB + 127) / 128, 256>>>(Wo, bo, out);
}

// round 6
// speedup vs baseline: 4.1967x; 1.2793x over previous
#include <cuda_runtime.h>
#include <cuda_fp16.h>
#include <math.h>
#include <cstdint>

// ---------------- problem constants ----------------
constexpr int BATCH = 64;
constexpr int TFULL = 2049;
constexpr int TCTX  = 2048;
constexpr int D     = 512;
constexpr int D2    = 1024;
constexpr int VOCAB = 50257;
constexpr int MTOK  = BATCH * TFULL;   // 131136

// ---------------- scratch (device globals) ----------------
__device__ float   g_H  [(size_t)MTOK * D];    // h, then x = h + ff
__device__ __half  g_Hh [(size_t)MTOK * D];
__device__ __half  g_Hl [(size_t)MTOK * D];
__device__ __half  g_A1h[(size_t)MTOK * D2];
__device__ __half  g_A1l[(size_t)MTOK * D2];
__device__ __half  g_W1h[(size_t)D2 * D];      // W1^T fp16  [N=D2, K=D]
__device__ __half  g_W2h[(size_t)D * D2];      // W2^T fp16  [N=D,  K=D2]
__device__ float   g_HID[(size_t)MTOK * D];
__device__ float   g_PERT[BATCH * TCTX];
__device__ int     g_IDX [BATCH * 3];
__device__ float   g_CTX [BATCH * D];

// ---------------- PTX helpers (base-target features only) ----------------
__device__ __forceinline__ unsigned smem_u32(const void* p) {
    unsigned a;
    asm("{ .reg .u64 t; cvta.to.shared.u64 t, %1; cvt.u32.u64 %0, t; }" : "=r"(a) : "l"(p));
    return a;
}
__device__ __forceinline__ void cp16(unsigned dst, const void* src, int sz) {
    asm volatile("cp.async.cg.shared.global [%0], [%1], 16, %2;"
                 :: "r"(dst), "l"(src), "r"(sz) : "memory");
}
__device__ __forceinline__ void ldsm4(unsigned& r0, unsigned& r1, unsigned& r2, unsigned& r3,
                                      unsigned addr) {
    asm volatile("ldmatrix.sync.aligned.m8n8.x4.shared.b16 {%0,%1,%2,%3}, [%4];"
                 : "=r"(r0), "=r"(r1), "=r"(r2), "=r"(r3) : "r"(addr));
}
__device__ __forceinline__ void mma_f16(float* c, const unsigned* a, const unsigned* b) {
    asm volatile("mma.sync.aligned.m16n8k16.row.col.f32.f16.f16.f32 "
                 "{%0,%1,%2,%3}, {%4,%5,%6,%7}, {%8,%9}, {%0,%1,%2,%3};"
                 : "+f"(c[0]), "+f"(c[1]), "+f"(c[2]), "+f"(c[3])
                 : "r"(a[0]), "r"(a[1]), "r"(a[2]), "r"(a[3]), "r"(b[0]), "r"(b[1]));
}
__device__ __forceinline__ void split_pack_h(float v0, float v1, unsigned& ph, unsigned& pl) {
    __half h0 = __float2half_rn(v0);
    __half h1 = __float2half_rn(v1);
    __half l0 = __float2half_rn(v0 - __half2float(h0));
    __half l1 = __float2half_rn(v1 - __half2float(h1));
    ph = (unsigned)__half_as_ushort(h0) | ((unsigned)__half_as_ushort(h1) << 16);
    pl = (unsigned)__half_as_ushort(l0) | ((unsigned)__half_as_ushort(l1) << 16);
}

// ---------------- weight prep: transpose + fp16 round ----------------
__global__ void wprep(const float* __restrict__ W, __half* __restrict__ Bh, int K, int N)
{
    int i = blockIdx.x * 256 + threadIdx.x;
    if (i >= K * N) return;
    int k = i / N, n = i - k * N;
    Bh[(size_t)n * K + k] = __float2half_rn(W[i]);
}

// ---------------- gather: warp-per-row embed lookup + fp16 split ----------------
__global__ __launch_bounds__(256) void gather_kernel(const int* __restrict__ seq,
                                                     const float* __restrict__ embed)
{
    int w = threadIdx.x >> 5, lane = threadIdx.x & 31;
    int m = blockIdx.x * 8 + w;             // MTOK divisible by 8
    int tok = seq[m];
    const float4* src = reinterpret_cast<const float4*>(embed + (size_t)tok * D);
    float4* dstH = reinterpret_cast<float4*>(g_H + (size_t)m * D);
    uint2* dstHh = reinterpret_cast<uint2*>(g_Hh + (size_t)m * D);
    uint2* dstHl = reinterpret_cast<uint2*>(g_Hl + (size_t)m * D);
    #pragma unroll
    for (int i = 0; i < 4; i++) {
        int j = lane + 32 * i;
        float4 v = src[j];
        dstH[j] = v;
        unsigned h0, l0, h1, l1;
        split_pack_h(v.x, v.y, h0, l0);
        split_pack_h(v.z, v.w, h1, l1);
        dstHh[j] = make_uint2(h0, h1);
        dstHl[j] = make_uint2(l0, l1);
    }
}

// ---------------- mma.sync split-fp16 GEMM (2 passes) ----------------
// C = A @ B^T (+bias, epilogue). A: [M,K] fp16 hi/lo, B: [N,K] fp16.
// CTA tile 128x128, 8 warps (4M x 2N), warp tile 32x64, BK=32, 4-stage cp.async.
// Per-stage: Ah[2][128][16] (8KB) + Al (8KB) + B (8KB) = 24KB.
// Slice layout: elem (row, k) of slice s at  s*4096 + row*32 + (k%16)*2  (bytes).
constexpr int STAGE_BYTES = 24576;
constexpr int GEMM_SMEM   = 4 * STAGE_BYTES;   // 98304 -> two CTAs per SM

__device__ __forceinline__ void fill_stage(unsigned sb,
    const __half* __restrict__ Ah, const __half* __restrict__ Al,
    const __half* __restrict__ Bh,
    int K, int m0, int M, int n0, int kc, int tid)
{
    int m = tid >> 1, half = tid & 1;
    int arow = m0 + m;
    int asz  = (arow < M) ? 16 : 0;
    size_t aoff = (size_t)(asz ? arow : 0) * K + kc + half * 8;
    size_t boff = (size_t)(n0 + m) * K + kc + half * 8;
    unsigned dst = sb + m * 32 + half * 16;
    #pragma unroll
    for (int s = 0; s < 2; s++) {
        cp16(dst + s * 4096,          Ah + aoff + s * 16, asz);
        cp16(dst + 8192 + s * 4096,   Al + aoff + s * 16, asz);
        cp16(dst + 16384 + s * 4096,  Bh + boff + s * 16, 16);
    }
    asm volatile("cp.async.commit_group;" ::: "memory");
}

// MODE 0: relu + fp16 hi/lo split out.  MODE 1: + bias + addsrc, fp32 out.
template<int MODE>
__global__ __launch_bounds__(256, 2) void ff_gemm(
    const __half* __restrict__ Ah, const __half* __restrict__ Al,
    const __half* __restrict__ Bh,
    const float* __restrict__ bias, const float* __restrict__ addsrc,
    __half* __restrict__ Ch, __half* __restrict__ Cl,
    float* __restrict__ Cf, int M, int N, int K)
{
    extern __shared__ __align__(128) char smem[];
    unsigned sb = smem_u32(smem);
    const int tid = threadIdx.x, lane = tid & 31, wid = tid >> 5;
    const int wm = wid & 3, wn = wid >> 2;
    const int m0 = blockIdx.y * 128, n0 = blockIdx.x * 128;

    // per-lane ldmatrix offsets (within a k-slice)
    const unsigned aO = (unsigned)((wm * 32 + (lane & 15)) * 32 + (lane >> 4) * 16);
    const unsigned bO = 16384u +
        (unsigned)((wn * 64 + (lane >> 4) * 8 + (lane & 7)) * 32 + ((lane >> 3) & 1) * 16);

    float acc[2][8][4];
    #pragma unroll
    for (int i = 0; i < 2; i++)
        #pragma unroll
        for (int j = 0; j < 8; j++)
            #pragma unroll
            for (int q = 0; q < 4; q++) acc[i][j][q] = 0.f;

    const int NC = K >> 5;
    fill_stage(sb + 0 * STAGE_BYTES, Ah, Al, Bh, K, m0, M, n0, 0,  tid);
    fill_stage(sb + 1 * STAGE_BYTES, Ah, Al, Bh, K, m0, M, n0, 32, tid);
    fill_stage(sb + 2 * STAGE_BYTES, Ah, Al, Bh, K, m0, M, n0, 64, tid);

    int sidx = 0;
    for (int c = 0; c < NC; c++) {
        int rem = NC - 1 - c;
        if (rem >= 3)      asm volatile("cp.async.wait_group 3;" ::: "memory");
        else if (rem == 2) asm volatile("cp.async.wait_group 2;" ::: "memory");
        else if (rem == 1) asm volatile("cp.async.wait_group 1;" ::: "memory");
        else               asm volatile("cp.async.wait_group 0;" ::: "memory");
        __syncthreads();

        int pf = c + 3;
        if (pf < NC) {
            int psidx = sidx + 3; if (psidx >= 4) psidx -= 4;
            fill_stage(sb + psidx * STAGE_BYTES, Ah, Al, Bh, K, m0, M, n0, pf * 32, tid);
        }

        unsigned st = sb + sidx * STAGE_BYTES;
        #pragma unroll
        for (int ks = 0; ks < 2; ks++) {
            unsigned sl = st + ks * 4096;
            unsigned ah[2][4], al[2][4], bh[8][2];
            #pragma unroll
            for (int mt = 0; mt < 2; mt++) {
                ldsm4(ah[mt][0], ah[mt][1], ah[mt][2], ah[mt][3], sl + aO + mt * 512);
                ldsm4(al[mt][0], al[mt][1], al[mt][2], al[mt][3], sl + 8192 + aO + mt * 512);
            }
            #pragma unroll
            for (int pr = 0; pr < 4; pr++)
                ldsm4(bh[2*pr][0], bh[2*pr][1], bh[2*pr+1][0], bh[2*pr+1][1],
                      sl + bO + pr * 512);
            #pragma unroll
            for (int mt = 0; mt < 2; mt++)
                #pragma unroll
                for (int nt = 0; nt < 8; nt++)
                    mma_f16(acc[mt][nt], ah[mt], bh[nt]);
            #pragma unroll
            for (int mt = 0; mt < 2; mt++)
                #pragma unroll
                for (int nt = 0; nt < 8; nt++)
                    mma_f16(acc[mt][nt], al[mt], bh[nt]);
        }
        if (++sidx == 4) sidx = 0;
    }

    // ---------------- epilogue ----------------
    const int g = lane >> 2, t4 = lane & 3;
    #pragma unroll
    for (int mt = 0; mt < 2; mt++) {
        int r0 = m0 + wm * 32 + mt * 16 + g;
        #pragma unroll
        for (int nt = 0; nt < 8; nt++) {
            int n = n0 + wn * 64 + nt * 8 + t4 * 2;
            float b0 = bias[n], b1 = bias[n + 1];
            if (MODE == 0) {
                if (r0 < M) {
                    float v0 = fmaxf(acc[mt][nt][0] + b0, 0.f);
                    float v1 = fmaxf(acc[mt][nt][1] + b1, 0.f);
                    unsigned ph, pl; split_pack_h(v0, v1, ph, pl);
                    *reinterpret_cast<unsigned*>(Ch + (size_t)r0 * N + n) = ph;
                    *reinterpret_cast<unsigned*>(Cl + (size_t)r0 * N + n) = pl;
                }
                if (r0 + 8 < M) {
                    float v0 = fmaxf(acc[mt][nt][2] + b0, 0.f);
                    float v1 = fmaxf(acc[mt][nt][3] + b1, 0.f);
                    unsigned ph, pl; split_pack_h(v0, v1, ph, pl);
                    *reinterpret_cast<unsigned*>(Ch + (size_t)(r0 + 8) * N + n) = ph;
                    *reinterpret_cast<unsigned*>(Cl + (size_t)(r0 + 8) * N + n) = pl;
                }
            } else {
                if (r0 < M) {
                    float2 a = *reinterpret_cast<const float2*>(addsrc + (size_t)r0 * N + n);
                    float2 o = make_float2(acc[mt][nt][0] + b0 + a.x,
                                           acc[mt][nt][1] + b1 + a.y);
                    *reinterpret_cast<float2*>(Cf + (size_t)r0 * N + n) = o;
                }
                if (r0 + 8 < M) {
                    float2 a = *reinterpret_cast<const float2*>(addsrc + (size_t)(r0 + 8) * N + n);
                    float2 o = make_float2(acc[mt][nt][2] + b0 + a.x,
                                           acc[mt][nt][3] + b1 + a.y);
                    *reinterpret_cast<float2*>(Cf + (size_t)(r0 + 8) * N + n) = o;
                }
            }
        }
    }
}

// ---------------- layernorm + gate + perturb (warp-per-row) ----------------
__global__ __launch_bounds__(256) void ln_gate_kernel(
    const float* __restrict__ gamma, const float* __restrict__ beta,
    const float* __restrict__ Wg, const float* __restrict__ bgp,
    const float* __restrict__ gumbel, const float* __restrict__ temp)
{
    int w = threadIdx.x >> 5, lane = threadIdx.x & 31;
    int m = blockIdx.x * 8 + w;             // MTOK divisible by 8
    const float4* x4 = reinterpret_cast<const float4*>(g_H + (size_t)m * D);
    const float4* g4 = reinterpret_cast<const float4*>(gamma);
    const float4* b4 = reinterpret_cast<const float4*>(beta);
    const float4* w4 = reinterpret_cast<const float4*>(Wg);
    float4* hid4 = reinterpret_cast<float4*>(g_HID + (size_t)m * D);

    float4 xv[4];
    float s = 0.f, q = 0.f;
    #pragma unroll
    for (int i = 0; i < 4; i++) {
        float4 v = x4[lane + 32 * i];
        xv[i] = v;
        s += v.x + v.y + v.z + v.w;
        q += v.x*v.x + v.y*v.y + v.z*v.z + v.w*v.w;
    }
    #pragma unroll
    for (int o = 16; o > 0; o >>= 1) {
        s += __shfl_xor_sync(0xffffffffu, s, o);
        q += __shfl_xor_sync(0xffffffffu, q, o);
    }
    float mu = s * (1.f / 512.f);
    float rs = rsqrtf(q * (1.f / 512.f) - mu * mu + 1e-5f);

    float gsum = 0.f;
    #pragma unroll
    for (int i = 0; i < 4; i++) {
        int j = lane + 32 * i;
        float4 gm = g4[j], bt = b4[j], wg = w4[j], v = xv[i];
        float4 h;
        h.x = (v.x - mu) * rs * gm.x + bt.x;
        h.y = (v.y - mu) * rs * gm.y + bt.y;
        h.z = (v.z - mu) * rs * gm.z + bt.z;
        h.w = (v.w - mu) * rs * gm.w + bt.w;
        hid4[j] = h;
        gsum += h.x*wg.x + h.y*wg.y + h.z*wg.z + h.w*wg.w;
    }
    #pragma unroll
    for (int o = 16; o > 0; o >>= 1)
        gsum += __shfl_xor_sync(0xffffffffu, gsum, o);
    if (lane == 0) {
        int b = m / TFULL, t = m - b * TFULL;
        if (t < TCTX)
            g_PERT[b * TCTX + t] = (gsum + bgp[0] + gumbel[b * TCTX + t]) / temp[0];
    }
}

// ---------------- per-row top-3 ----------------
__global__ void top3_kernel()
{
    int b = blockIdx.x, tid = threadIdx.x;   // 256 threads
    float bv[3] = {-1e30f, -1e30f, -1e30f};
    int   bi[3] = {0, 0, 0};
    for (int t = tid; t < TCTX; t += 256) {
        float v = g_PERT[b * TCTX + t];
        if (v > bv[0]) { bv[2]=bv[1]; bi[2]=bi[1]; bv[1]=bv[0]; bi[1]=bi[0]; bv[0]=v; bi[0]=t; }
        else if (v > bv[1]) { bv[2]=bv[1]; bi[2]=bi[1]; bv[1]=v; bi[1]=t; }
        else if (v > bv[2]) { bv[2]=v; bi[2]=t; }
    }
    __shared__ float sv[768];
    __shared__ int   si[768];
    sv[tid*3+0]=bv[0]; sv[tid*3+1]=bv[1]; sv[tid*3+2]=bv[2];
    si[tid*3+0]=bi[0]; si[tid*3+1]=bi[1]; si[tid*3+2]=bi[2];
    __syncthreads();
    if (tid == 0) {
        float rv[3] = {-1e30f, -1e30f, -1e30f};
        int   ri[3] = {0, 0, 0};
        for (int e = 0; e < 768; e++) {
            float v = sv[e]; int i = si[e];
            if (v > rv[0]) { rv[2]=rv[1]; ri[2]=ri[1]; rv[1]=rv[0]; ri[1]=ri[0]; rv[0]=v; ri[0]=i; }
            else if (v > rv[1]) { rv[2]=rv[1]; ri[2]=ri[1]; rv[1]=v; ri[1]=i; }
            else if (v > rv[2]) { rv[2]=v; ri[2]=i; }
        }
        g_IDX[b*3+0]=ri[0]; g_IDX[b*3+1]=ri[1]; g_IDX[b*3+2]=ri[2];
    }
}

// ---------------- memory attention ----------------
__global__ __launch_bounds__(512) void attn_kernel(
    const float* __restrict__ Wr, const float* __restrict__ br)
{
    int b = blockIdx.x, tid = threadIdx.x;   // 512 threads (one per d)
    __shared__ float hlast[D];
    __shared__ float gh[3][D];
    __shared__ float red[48];
    __shared__ float s_attn[3];
    size_t base = (size_t)b * TFULL * D;
    hlast[tid] = g_HID[base + (size_t)TCTX * D + tid];
    int i0 = g_IDX[b*3+0], i1 = g_IDX[b*3+1], i2 = g_IDX[b*3+2];
    gh[0][tid] = g_HID[base + (size_t)i0 * D + tid];
    gh[1][tid] = g_HID[base + (size_t)i1 * D + tid];
    gh[2][tid] = g_HID[base + (size_t)i2 * D + tid];
    __syncthreads();

    float qv = br[tid];
    #pragma unroll 4
    for (int j = 0; j < D; j++)
        qv += hlast[j] * Wr[(size_t)j * D + tid];

    float p0 = gh[0][tid] * qv, p1 = gh[1][tid] * qv, p2 = gh[2][tid] * qv;
    #pragma unroll
    for (int o = 16; o > 0; o >>= 1) {
        p0 += __shfl_down_sync(0xffffffffu, p0, o);
        p1 += __shfl_down_sync(0xffffffffu, p1, o);
        p2 += __shfl_down_sync(0xffffffffu, p2, o);
    }
    int lane = tid & 31, w = tid >> 5;
    if (lane == 0) { red[w] = p0; red[16 + w] = p1; red[32 + w] = p2; }
    __syncthreads();
    if (tid == 0) {
        float s0 = 0.f, s1 = 0.f, s2 = 0.f;
        for (int i = 0; i < 16; i++) { s0 += red[i]; s1 += red[16+i]; s2 += red[32+i]; }
        float mx = fmaxf(fmaxf(s0, s1), fmaxf(s2, 0.f));
        float e0 = expf(s0 - mx), e1 = expf(s1 - mx), e2 = expf(s2 - mx);
        float den = e0 + e1 + e2 + 13.f * expf(-mx);
        s_attn[0] = e0 / den; s_attn[1] = e1 / den; s_attn[2] = e2 / den;
    }
    __syncthreads();
    g_CTX[b * D + tid] = s_attn[0]*gh[0][tid] + s_attn[1]*gh[1][tid] + s_attn[2]*gh[2][tid];
}

// ---------------- out = ctx @ Wo + bo  (64 x 50257, K=512), Wo read ONCE ----------------
__global__ __launch_bounds__(256) void out_gemm(
    const float* __restrict__ Wo, const float* __restrict__ bo,
    float* __restrict__ out)
{
    __shared__ float sc[64 * 64];            // 64 rows x 64 k-chunk
    int tid = threadIdx.x;
    int n  = blockIdx.x * 128 + (tid & 127);
    int rh = tid >> 7;                       // 0 or 1 -> rows [0,32) or [32,64)
    bool valid = (n < VOCAB);

    float acc[32];
    #pragma unroll
    for (int r = 0; r < 32; r++) acc[r] = 0.f;

    for (int k0 = 0; k0 < 512; k0 += 64) {
        __syncthreads();
        #pragma unroll
        for (int i = tid; i < 64 * 64; i += 256) {
            int row = i >> 6, k = i & 63;
            sc[i] = g_CTX[row * 512 + k0 + k];
        }
        __syncthreads();
        if (valid) {
            const float* scr = sc + rh * 32 * 64;
            #pragma unroll 4
            for (int k = 0; k < 64; k++) {
                float w = Wo[(size_t)(k0 + k) * VOCAB + n];
                #pragma unroll
                for (int r = 0; r < 32; r++)
                    acc[r] += scr[r * 64 + k] * w;
            }
        }
    }
    if (valid) {
        float b = bo[n];
        #pragma unroll
        for (int r = 0; r < 32; r++)
            out[(size_t)(rh * 32 + r) * VOCAB + n] = acc[r] + b;
    }
}

// ---------------- launch ----------------
extern "C" void kernel_launch(void* const* d_in, const int* in_sizes, int n_in,
                              void* d_out, int out_size)
{
    const int*   seq    = (const int*)  d_in[0];
    const float* temp   = (const float*)d_in[1];
    const float* gumbel = (const float*)d_in[2];
    const float* embed  = (const float*)d_in[3];
    const float* W1     = (const float*)d_in[4];
    const float* b1     = (const float*)d_in[5];
    const float* W2     = (const float*)d_in[6];
    const float* b2     = (const float*)d_in[7];
    const float* gamma  = (const float*)d_in[8];
    const float* beta   = (const float*)d_in[9];
    const float* Wg     = (const float*)d_in[10];
    const float* bg     = (const float*)d_in[11];
    const float* Wr     = (const float*)d_in[12];
    const float* br     = (const float*)d_in[13];
    const float* Wo     = (const float*)d_in[14];
    const float* bo     = (const float*)d_in[15];
    float* out = (float*)d_out;

    float *pH;
    __half *pHh, *pHl, *pA1h, *pA1l, *pW1h, *pW2h;
    cudaGetSymbolAddress((void**)&pH,   g_H);
    cudaGetSymbolAddress((void**)&pHh,  g_Hh);
    cudaGetSymbolAddress((void**)&pHl,  g_Hl);
    cudaGetSymbolAddress((void**)&pA1h, g_A1h);
    cudaGetSymbolAddress((void**)&pA1l, g_A1l);
    cudaGetSymbolAddress((void**)&pW1h, g_W1h);
    cudaGetSymbolAddress((void**)&pW2h, g_W2h);

    cudaFuncSetAttribute(ff_gemm<0>, cudaFuncAttributeMaxDynamicSharedMemorySize, GEMM_SMEM);
    cudaFuncSetAttribute(ff_gemm<1>, cudaFuncAttributeMaxDynamicSharedMemorySize, GEMM_SMEM);

    // 0. weight prep (transpose + fp16 round)
    wprep<<<(D * D2 + 255) / 256, 256>>>(W1, pW1h, D, D2);
    wprep<<<(D2 * D + 255) / 256, 256>>>(W2, pW2h, D2, D);

    // 1. gather embeddings (+ fp16 split), warp per row
    gather_kernel<<<MTOK / 8, 256>>>(seq, embed);

    const int MT = (MTOK + 127) / 128;   // 1025

    // 2. A1 = relu(H @ W1 + b1) -> fp16 hi/lo
    ff_gemm<0><<<dim3(D2 / 128, MT), 256, GEMM_SMEM>>>(
        pHh, pHl, pW1h, b1, nullptr, pA1h, pA1l, nullptr, MTOK, D2, D);

    // 3. X = A1 @ W2 + b2 + H  (fp32, into g_H)
    ff_gemm<1><<<dim3(D / 128, MT), 256, GEMM_SMEM>>>(
        pA1h, pA1l, pW2h, b2, pH, nullptr, nullptr, pH, MTOK, D, D2);

    // 4. layernorm + gate + perturb, warp per row
    ln_gate_kernel<<<MTOK / 8, 256>>>(gamma, beta, Wg, bg, gumbel, temp);

    // 5. top-3 per batch row
    top3_kernel<<<BATCH, 256>>>();

    // 6. memory attention -> ctx
    attn_kernel<<<BATCH, 512>>>(Wr, br);

    // 7. out = ctx @ Wo + bo
    out_gemm<<<(VOCAB + 127) / 128, 256>>>(Wo, bo, out);
}